// round 3
// baseline (speedup 1.0000x reference)
#include <cuda_runtime.h>
#include <math.h>

#define NN 50000
#define TT 4
#define FF 128
#define EE 800000

// ---------------- scratch (static device globals; no allocation) ----------------
__device__ int   g_deg[NN];
__device__ float g_dinv[NN];
__device__ int   g_cnt[NN];
__device__ int   g_rowoff[NN + 1];
__device__ int   g_cursor[NN];
__device__ int   g_col[EE];
__device__ float g_w[EE];
__device__ float g_Tx1[(size_t)NN * FF];
__device__ float g_Tx2[(size_t)NN * FF];
__device__ float g_H[(size_t)NN * FF];
__device__ float g_Gx[(size_t)NN * 384];
__device__ float g_Gh[(size_t)NN * 256];
__device__ float g_Ghh[(size_t)NN * FF];
__device__ float g_Z[(size_t)NN * FF];
__device__ float g_HR[(size_t)NN * FF];
__device__ float g_D1[(size_t)NN * FF];
__device__ float g_WxP[384 * 384];
__device__ float g_WhP[384 * 256];
__device__ float g_bx[384];
__device__ float g_bh[256];

// ---------------- small helpers ----------------
__device__ __forceinline__ unsigned long long ffma2(unsigned long long a,
                                                    unsigned long long b,
                                                    unsigned long long c) {
    unsigned long long d;
    asm("fma.rn.f32x2 %0, %1, %2, %3;" : "=l"(d) : "l"(a), "l"(b), "l"(c));
    return d;
}
__device__ __forceinline__ unsigned long long pack2(float x, float y) {
    unsigned long long r;
    asm("mov.b64 %0, {%1, %2};" : "=l"(r) : "f"(x), "f"(y));
    return r;
}
__device__ __forceinline__ float2 unpack2(unsigned long long v) {
    float lo, hi;
    asm("mov.b64 {%0, %1}, %2;" : "=f"(lo), "=f"(hi) : "l"(v));
    return make_float2(lo, hi);
}

// ---------------- graph preprocessing (edge_index is int32!) ----------------
__global__ void k_deg(const int* __restrict__ src, int* __restrict__ deg, int E) {
    int i = blockIdx.x * blockDim.x + threadIdx.x;
    if (i < E) {
        unsigned s = (unsigned)src[i];
        if (s < NN) atomicAdd(&deg[s], 1);
    }
}
__global__ void k_cnt(const int* __restrict__ dst, int* __restrict__ cnt, int E) {
    int i = blockIdx.x * blockDim.x + threadIdx.x;
    if (i < E) {
        unsigned d = (unsigned)dst[i];
        if (d < NN) atomicAdd(&cnt[d], 1);
    }
}
__global__ void k_dinv(const int* __restrict__ deg, float* __restrict__ dinv, int n) {
    int i = blockIdx.x * blockDim.x + threadIdx.x;
    if (i < n) {
        int d = deg[i];
        dinv[i] = d > 0 ? rsqrtf((float)d) : 0.0f;
    }
}
__global__ void k_scan(const int* __restrict__ cnt, int* __restrict__ rowoff, int n) {
    __shared__ int sums[1024];
    int tid = threadIdx.x;
    int chunk = (n + 1023) >> 10;
    int s0 = tid * chunk;
    int s1 = min(s0 + chunk, n);
    int s = 0;
    for (int i = s0; i < s1; i++) s += cnt[i];
    sums[tid] = s;
    __syncthreads();
    for (int off = 1; off < 1024; off <<= 1) {
        int v = (tid >= off) ? sums[tid - off] : 0;
        __syncthreads();
        sums[tid] += v;
        __syncthreads();
    }
    int run = (tid == 0) ? 0 : sums[tid - 1];
    for (int i = s0; i < s1; i++) { rowoff[i] = run; run += cnt[i]; }
    if (tid == 1023) rowoff[n] = sums[1023];
}
__global__ void k_scatter(const int* __restrict__ src, const int* __restrict__ dst,
                          const float* __restrict__ dinv, int* __restrict__ cursor,
                          int* __restrict__ col, float* __restrict__ w, int E) {
    int i = blockIdx.x * blockDim.x + threadIdx.x;
    if (i < E) {
        unsigned s = (unsigned)src[i];
        unsigned d = (unsigned)dst[i];
        if (s < NN && d < NN) {
            int pos = atomicAdd(&cursor[d], 1);
            col[pos] = (int)s;
            w[pos] = -dinv[s] * dinv[d];
        }
    }
}

// ---------------- SpMM: Y[r] = sum_e w[e]*X[col[e]]  (optionally 2*sum - base) ----------------
__global__ void k_spmm(const int* __restrict__ rowoff, const int* __restrict__ col,
                       const float* __restrict__ w, const float* __restrict__ X,
                       const float* __restrict__ base, float* __restrict__ Y, int n) {
    int r = blockIdx.x * blockDim.y + threadIdx.y;
    if (r >= n) return;
    int f = threadIdx.x;  // 0..127
    int e0 = rowoff[r], e1 = rowoff[r + 1];
    float acc = 0.f;
    int e = e0;
    for (; e + 4 <= e1; e += 4) {
        int c0 = col[e], c1 = col[e + 1], c2 = col[e + 2], c3 = col[e + 3];
        float w0 = w[e], w1 = w[e + 1], w2 = w[e + 2], w3 = w[e + 3];
        acc += w0 * X[(size_t)c0 * FF + f];
        acc += w1 * X[(size_t)c1 * FF + f];
        acc += w2 * X[(size_t)c2 * FF + f];
        acc += w3 * X[(size_t)c3 * FF + f];
    }
    for (; e < e1; e++) acc += w[e] * X[(size_t)col[e] * FF + f];
    size_t o = (size_t)r * FF + f;
    if (base) Y[o] = 2.f * acc - base[o];
    else      Y[o] = acc;
}

// ---------------- GEMM: C(n x No) = [A0|A1|A2](n x nchunks*128) @ B(K x No) + bias ----------------
// BM=128, BN=64, BK=16, 256 threads, 8x4 per thread, packed f32x2 FMAs.
__global__ void __launch_bounds__(256) k_gemm(
    const float* __restrict__ A0, const float* __restrict__ A1, const float* __restrict__ A2,
    int nchunks, const float* __restrict__ B, const float* __restrict__ bias,
    float* __restrict__ C, int n, int No, int act) {
    __shared__ float As[16][128];
    __shared__ float Bs[16][64];
    const float* Ap[3] = {A0, A1, A2};
    int m0 = blockIdx.x * 128;
    int n0 = blockIdx.y * 64;
    int t = threadIdx.x;
    int ty = t >> 4, tx = t & 15;

    unsigned long long acc[4][4];
#pragma unroll
    for (int i = 0; i < 4; i++)
#pragma unroll
        for (int j = 0; j < 4; j++) acc[i][j] = 0ull;

    int K = nchunks * 128;
    for (int k0 = 0; k0 < K; k0 += 16) {
        const float* A = Ap[k0 >> 7];
        int lk = k0 & 127;
#pragma unroll
        for (int rep = 0; rep < 2; rep++) {
            int f = t + rep * 256;        // 0..511
            int row = f >> 2;
            int kq = (f & 3) * 4;
            float4 v = make_float4(0.f, 0.f, 0.f, 0.f);
            int gr = m0 + row;
            if (gr < n) v = *(const float4*)(A + (size_t)gr * 128 + lk + kq);
            As[kq + 0][row] = v.x;
            As[kq + 1][row] = v.y;
            As[kq + 2][row] = v.z;
            As[kq + 3][row] = v.w;
        }
        {
            int row = t >> 4;
            int cq = (t & 15) * 4;
            *(float4*)&Bs[row][cq] = *(const float4*)(B + (size_t)(k0 + row) * No + n0 + cq);
        }
        __syncthreads();
#pragma unroll
        for (int kk = 0; kk < 16; kk++) {
            float4 b = *(const float4*)(&Bs[kk][tx * 4]);
            unsigned long long bb0 = pack2(b.x, b.x);
            unsigned long long bb1 = pack2(b.y, b.y);
            unsigned long long bb2 = pack2(b.z, b.z);
            unsigned long long bb3 = pack2(b.w, b.w);
            union UU { float4 f; unsigned long long u[2]; } ua, ub;
            ua.f = *(const float4*)(&As[kk][ty * 8]);
            ub.f = *(const float4*)(&As[kk][ty * 8 + 4]);
            unsigned long long av[4] = {ua.u[0], ua.u[1], ub.u[0], ub.u[1]};
#pragma unroll
            for (int ip = 0; ip < 4; ip++) {
                acc[ip][0] = ffma2(av[ip], bb0, acc[ip][0]);
                acc[ip][1] = ffma2(av[ip], bb1, acc[ip][1]);
                acc[ip][2] = ffma2(av[ip], bb2, acc[ip][2]);
                acc[ip][3] = ffma2(av[ip], bb3, acc[ip][3]);
            }
        }
        __syncthreads();
    }
    float4 bv = *(const float4*)(bias + n0 + tx * 4);
#pragma unroll
    for (int ip = 0; ip < 4; ip++) {
        float2 c0 = unpack2(acc[ip][0]);
        float2 c1 = unpack2(acc[ip][1]);
        float2 c2 = unpack2(acc[ip][2]);
        float2 c3 = unpack2(acc[ip][3]);
        int r0 = m0 + ty * 8 + ip * 2;
        if (r0 < n) {
            float4 o = make_float4(c0.x + bv.x, c1.x + bv.y, c2.x + bv.z, c3.x + bv.w);
            if (act) { o.x = fmaxf(o.x, 0.f); o.y = fmaxf(o.y, 0.f); o.z = fmaxf(o.z, 0.f); o.w = fmaxf(o.w, 0.f); }
            *(float4*)(C + (size_t)r0 * No + n0 + tx * 4) = o;
        }
        if (r0 + 1 < n) {
            float4 o = make_float4(c0.y + bv.x, c1.y + bv.y, c2.y + bv.z, c3.y + bv.w);
            if (act) { o.x = fmaxf(o.x, 0.f); o.y = fmaxf(o.y, 0.f); o.z = fmaxf(o.z, 0.f); o.w = fmaxf(o.w, 0.f); }
            *(float4*)(C + (size_t)(r0 + 1) * No + n0 + tx * 4) = o;
        }
    }
}

// ---------------- weight packing ----------------
__global__ void k_pack(const float* __restrict__ Wxz, const float* __restrict__ Wxr,
                       const float* __restrict__ Wxh, const float* __restrict__ Whz,
                       const float* __restrict__ Whr,
                       const float* __restrict__ bxz, const float* __restrict__ bxr,
                       const float* __restrict__ bxh, const float* __restrict__ bhz,
                       const float* __restrict__ bhr,
                       float* __restrict__ WxP, float* __restrict__ WhP,
                       float* __restrict__ bx, float* __restrict__ bh) {
    int i = blockIdx.x * blockDim.x + threadIdx.x;
    if (i < 384 * 384) {
        int row = i / 384, c = i % 384;
        float v;
        if (c < 128)      v = Wxz[row * 128 + c];
        else if (c < 256) v = Wxr[row * 128 + (c - 128)];
        else              v = Wxh[row * 128 + (c - 256)];
        WxP[i] = v;
    }
    if (i < 384 * 256) {
        int row = i / 256, c = i % 256;
        WhP[i] = (c < 128) ? Whz[row * 128 + c] : Whr[row * 128 + (c - 128)];
    }
    if (i < 384) bx[i] = (i < 128) ? bxz[i] : ((i < 256) ? bxr[i - 128] : bxh[i - 256]);
    if (i < 256) bh[i] = (i < 128) ? bhz[i] : bhr[i - 128];
}

// ---------------- gates ----------------
__global__ void k_gates1(const float* __restrict__ Gx, const float* __restrict__ Gh,
                         const float* __restrict__ H, float* __restrict__ Z,
                         float* __restrict__ HR, int total) {
    int i = blockIdx.x * blockDim.x + threadIdx.x;
    if (i >= total) return;
    int row = i >> 7, c = i & 127;
    size_t bxo = (size_t)row * 384, bho = (size_t)row * 256;
    float z = 1.f / (1.f + expf(-(Gx[bxo + c] + Gh[bho + c])));
    float r = 1.f / (1.f + expf(-(Gx[bxo + 128 + c] + Gh[bho + 128 + c])));
    Z[i] = z;
    HR[i] = H[i] * r;
}
__global__ void k_gates2(const float* __restrict__ Gx, const float* __restrict__ Ghh,
                         const float* __restrict__ Z, float* __restrict__ H, int total) {
    int i = blockIdx.x * blockDim.x + threadIdx.x;
    if (i >= total) return;
    int row = i >> 7, c = i & 127;
    float ht = tanhf(Gx[(size_t)row * 384 + 256 + c] + Ghh[i]);
    float z = Z[i];
    H[i] = z * H[i] + (1.f - z) * ht;
}

// ---------------- driver ----------------
extern "C" void kernel_launch(void* const* d_in, const int* in_sizes, int n_in,
                              void* d_out, int out_size) {
    const float* x   = (const float*)d_in[0];
    const int*   ei  = (const int*)d_in[1];   // JAX default x64-disabled: int32
    const float* Wxz = (const float*)d_in[2];
    const float* Whz = (const float*)d_in[3];
    const float* Wxr = (const float*)d_in[4];
    const float* Whr = (const float*)d_in[5];
    const float* Wxh = (const float*)d_in[6];
    const float* Whh = (const float*)d_in[7];
    const float* bxz = (const float*)d_in[8];
    const float* bhz = (const float*)d_in[9];
    const float* bxr = (const float*)d_in[10];
    const float* bhr = (const float*)d_in[11];
    const float* bxh = (const float*)d_in[12];
    const float* bhh = (const float*)d_in[13];
    const float* Wd1 = (const float*)d_in[14];
    const float* bd1 = (const float*)d_in[15];
    const float* Wd2 = (const float*)d_in[16];
    const float* bd2 = (const float*)d_in[17];
    float* out = (float*)d_out;
    (void)in_sizes; (void)n_in; (void)out_size;

    int *p_deg, *p_cnt, *p_rowoff, *p_cursor, *p_col;
    float *p_dinv, *p_w, *p_Tx1, *p_Tx2, *p_H, *p_Gx, *p_Gh, *p_Ghh, *p_Z, *p_HR, *p_D1;
    float *p_WxP, *p_WhP, *p_bx, *p_bh;
    cudaGetSymbolAddress((void**)&p_deg, g_deg);
    cudaGetSymbolAddress((void**)&p_cnt, g_cnt);
    cudaGetSymbolAddress((void**)&p_rowoff, g_rowoff);
    cudaGetSymbolAddress((void**)&p_cursor, g_cursor);
    cudaGetSymbolAddress((void**)&p_col, g_col);
    cudaGetSymbolAddress((void**)&p_dinv, g_dinv);
    cudaGetSymbolAddress((void**)&p_w, g_w);
    cudaGetSymbolAddress((void**)&p_Tx1, g_Tx1);
    cudaGetSymbolAddress((void**)&p_Tx2, g_Tx2);
    cudaGetSymbolAddress((void**)&p_H, g_H);
    cudaGetSymbolAddress((void**)&p_Gx, g_Gx);
    cudaGetSymbolAddress((void**)&p_Gh, g_Gh);
    cudaGetSymbolAddress((void**)&p_Ghh, g_Ghh);
    cudaGetSymbolAddress((void**)&p_Z, g_Z);
    cudaGetSymbolAddress((void**)&p_HR, g_HR);
    cudaGetSymbolAddress((void**)&p_D1, g_D1);
    cudaGetSymbolAddress((void**)&p_WxP, g_WxP);
    cudaGetSymbolAddress((void**)&p_WhP, g_WhP);
    cudaGetSymbolAddress((void**)&p_bx, g_bx);
    cudaGetSymbolAddress((void**)&p_bh, g_bh);

    const int threads = 256;
    const int gE = (EE + threads - 1) / threads;
    const int gN = (NN + threads - 1) / threads;
    const int gNF = (NN * FF + threads - 1) / threads;
    dim3 spmmBlk(128, 2);
    int spmmGrid = (NN + 1) / 2;

    // pack weights + init H
    k_pack<<<(384 * 384 + threads - 1) / threads, threads>>>(
        Wxz, Wxr, Wxh, Whz, Whr, bxz, bxr, bxh, bhz, bhr, p_WxP, p_WhP, p_bx, p_bh);
    cudaMemsetAsync(p_H, 0, (size_t)NN * FF * sizeof(float));

    for (int t = 0; t < TT; t++) {
        const int* src = ei + (size_t)t * 2 * EE;
        const int* dst = src + EE;
        const float* xt = x + (size_t)t * NN * FF;

        // edge norm + CSR build
        cudaMemsetAsync(p_deg, 0, NN * sizeof(int));
        cudaMemsetAsync(p_cnt, 0, NN * sizeof(int));
        k_deg<<<gE, threads>>>(src, p_deg, EE);
        k_cnt<<<gE, threads>>>(dst, p_cnt, EE);
        k_dinv<<<gN, threads>>>(p_deg, p_dinv, NN);
        k_scan<<<1, 1024>>>(p_cnt, p_rowoff, NN);
        cudaMemcpyAsync(p_cursor, p_rowoff, NN * sizeof(int), cudaMemcpyDeviceToDevice);
        k_scatter<<<gE, threads>>>(src, dst, p_dinv, p_cursor, p_col, p_w, EE);

        // x path: Tx1 = L x, Tx2 = 2 L Tx1 - x, Gx = [x|Tx1|Tx2] @ WxP + bx
        k_spmm<<<spmmGrid, spmmBlk>>>(p_rowoff, p_col, p_w, xt, nullptr, p_Tx1, NN);
        k_spmm<<<spmmGrid, spmmBlk>>>(p_rowoff, p_col, p_w, p_Tx1, xt, p_Tx2, NN);
        {
            dim3 g((NN + 127) / 128, 384 / 64);
            k_gemm<<<g, 256>>>(xt, p_Tx1, p_Tx2, 3, p_WxP, p_bx, p_Gx, NN, 384, 0);
        }
        // H path
        k_spmm<<<spmmGrid, spmmBlk>>>(p_rowoff, p_col, p_w, p_H, nullptr, p_Tx1, NN);
        k_spmm<<<spmmGrid, spmmBlk>>>(p_rowoff, p_col, p_w, p_Tx1, p_H, p_Tx2, NN);
        {
            dim3 g((NN + 127) / 128, 256 / 64);
            k_gemm<<<g, 256>>>(p_H, p_Tx1, p_Tx2, 3, p_WhP, p_bh, p_Gh, NN, 256, 0);
        }
        // gates Z, R; HR = H*R
        k_gates1<<<gNF, threads>>>(p_Gx, p_Gh, p_H, p_Z, p_HR, NN * FF);
        // HR path
        k_spmm<<<spmmGrid, spmmBlk>>>(p_rowoff, p_col, p_w, p_HR, nullptr, p_Tx1, NN);
        k_spmm<<<spmmGrid, spmmBlk>>>(p_rowoff, p_col, p_w, p_Tx1, p_HR, p_Tx2, NN);
        {
            dim3 g((NN + 127) / 128, 128 / 64);
            k_gemm<<<g, 256>>>(p_HR, p_Tx1, p_Tx2, 3, Whh, bhh, p_Ghh, NN, 128, 0);
        }
        // H update
        k_gates2<<<gNF, threads>>>(p_Gx, p_Ghh, p_Z, p_H, NN * FF);
    }

    // decoder: out_xpred = relu(H@Wd1+bd1)@Wd2 + bd2 ; out second half = H
    {
        dim3 g((NN + 127) / 128, 128 / 64);
        k_gemm<<<g, 256>>>(p_H, nullptr, nullptr, 1, Wd1, bd1, p_D1, NN, 128, 1);
        k_gemm<<<g, 256>>>(p_D1, nullptr, nullptr, 1, Wd2, bd2, out, NN, 128, 0);
    }
    cudaMemcpyAsync(out + (size_t)NN * FF, p_H, (size_t)NN * FF * sizeof(float),
                    cudaMemcpyDeviceToDevice);
}

// round 5
// speedup vs baseline: 1.3033x; 1.3033x over previous
#include <cuda_runtime.h>
#include <cuda_bf16.h>
#include <cstdint>
#include <math.h>

#define NN 50000
#define TT 4
#define FF 128
#define EE 800000

// ---------------- scratch (static device globals; no allocation) ----------------
__device__ int   g_deg[NN];
__device__ float g_dinv[NN];
__device__ int   g_cnt[NN];
__device__ int   g_rowoff[NN + 1];
__device__ int   g_cursor[NN];
__device__ int   g_col[EE];
__device__ float g_w[EE];
__device__ float g_Tx1[(size_t)NN * FF];
__device__ float g_Tx2[(size_t)NN * FF];
__device__ float g_H[(size_t)NN * FF];
__device__ float g_Gx[(size_t)NN * 384];
__device__ float g_Gh[(size_t)NN * 256];
__device__ float g_Ghh[(size_t)NN * FF];
__device__ float g_Z[(size_t)NN * FF];
__device__ float g_HR[(size_t)NN * FF];
__device__ float g_D1[(size_t)NN * FF];
__device__ float g_WxT[384 * 384];   // [No=384][K=384]
__device__ float g_WhT[256 * 384];   // [No=256][K=384]
__device__ float g_WhhT[128 * 384];  // [No=128][K=384]
__device__ float g_Wd1T[128 * 128];
__device__ float g_Wd2T[128 * 128];
__device__ float g_bx[384];
__device__ float g_bh[256];

// ---------------- helpers ----------------
__device__ __forceinline__ uint32_t smem_u32(const void* p) {
    uint32_t a;
    asm("{ .reg .u64 t; cvta.to.shared.u64 t, %1; cvt.u32.u64 %0, t; }" : "=r"(a) : "l"(p));
    return a;
}
__device__ __forceinline__ void ldm_x4(uint32_t& r0, uint32_t& r1, uint32_t& r2, uint32_t& r3,
                                       uint32_t addr) {
    asm volatile("ldmatrix.sync.aligned.m8n8.x4.shared.b16 {%0,%1,%2,%3}, [%4];"
                 : "=r"(r0), "=r"(r1), "=r"(r2), "=r"(r3) : "r"(addr));
}
__device__ __forceinline__ void mma_bf16(float* d, const uint32_t* a, const uint32_t* b) {
    asm volatile(
        "mma.sync.aligned.m16n8k16.row.col.f32.bf16.bf16.f32 "
        "{%0,%1,%2,%3}, {%4,%5,%6,%7}, {%8,%9}, {%0,%1,%2,%3};"
        : "+f"(d[0]), "+f"(d[1]), "+f"(d[2]), "+f"(d[3])
        : "r"(a[0]), "r"(a[1]), "r"(a[2]), "r"(a[3]), "r"(b[0]), "r"(b[1]));
}
__device__ __forceinline__ void split2(float x, float y, uint32_t& h, uint32_t& l) {
    __nv_bfloat16 hx = __float2bfloat16(x), hy = __float2bfloat16(y);
    __nv_bfloat16 lx = __float2bfloat16(x - __bfloat162float(hx));
    __nv_bfloat16 ly = __float2bfloat16(y - __bfloat162float(hy));
    h = (uint32_t)__bfloat16_as_ushort(hx) | ((uint32_t)__bfloat16_as_ushort(hy) << 16);
    l = (uint32_t)__bfloat16_as_ushort(lx) | ((uint32_t)__bfloat16_as_ushort(ly) << 16);
}

// ---------------- graph preprocessing (edge_index is int32) ----------------
__global__ void k_deg(const int* __restrict__ src, int* __restrict__ deg, int E) {
    int i = blockIdx.x * blockDim.x + threadIdx.x;
    if (i < E) { unsigned s = (unsigned)src[i]; if (s < NN) atomicAdd(&deg[s], 1); }
}
__global__ void k_cnt(const int* __restrict__ dst, int* __restrict__ cnt, int E) {
    int i = blockIdx.x * blockDim.x + threadIdx.x;
    if (i < E) { unsigned d = (unsigned)dst[i]; if (d < NN) atomicAdd(&cnt[d], 1); }
}
__global__ void k_dinv(const int* __restrict__ deg, float* __restrict__ dinv, int n) {
    int i = blockIdx.x * blockDim.x + threadIdx.x;
    if (i < n) { int d = deg[i]; dinv[i] = d > 0 ? rsqrtf((float)d) : 0.0f; }
}
__global__ void k_scan(const int* __restrict__ cnt, int* __restrict__ rowoff, int n) {
    __shared__ int sums[1024];
    int tid = threadIdx.x;
    int chunk = (n + 1023) >> 10;
    int s0 = tid * chunk, s1 = min(s0 + chunk, n);
    int s = 0;
    for (int i = s0; i < s1; i++) s += cnt[i];
    sums[tid] = s;
    __syncthreads();
    for (int off = 1; off < 1024; off <<= 1) {
        int v = (tid >= off) ? sums[tid - off] : 0;
        __syncthreads();
        sums[tid] += v;
        __syncthreads();
    }
    int run = (tid == 0) ? 0 : sums[tid - 1];
    for (int i = s0; i < s1; i++) { rowoff[i] = run; run += cnt[i]; }
    if (tid == 1023) rowoff[n] = sums[1023];
}
__global__ void k_scatter(const int* __restrict__ src, const int* __restrict__ dst,
                          const float* __restrict__ dinv, int* __restrict__ cursor,
                          int* __restrict__ col, float* __restrict__ w, int E) {
    int i = blockIdx.x * blockDim.x + threadIdx.x;
    if (i < E) {
        unsigned s = (unsigned)src[i], d = (unsigned)dst[i];
        if (s < NN && d < NN) {
            int pos = atomicAdd(&cursor[d], 1);
            col[pos] = (int)s;
            w[pos] = -dinv[s] * dinv[d];
        }
    }
}

// ---------------- SpMM ----------------
__global__ void k_spmm(const int* __restrict__ rowoff, const int* __restrict__ col,
                       const float* __restrict__ w, const float* __restrict__ X,
                       const float* __restrict__ base, float* __restrict__ Y, int n) {
    int r = blockIdx.x * blockDim.y + threadIdx.y;
    if (r >= n) return;
    int f = threadIdx.x;
    int e0 = rowoff[r], e1 = rowoff[r + 1];
    float acc = 0.f;
    int e = e0;
    for (; e + 4 <= e1; e += 4) {
        int c0 = col[e], c1 = col[e + 1], c2 = col[e + 2], c3 = col[e + 3];
        float w0 = w[e], w1 = w[e + 1], w2 = w[e + 2], w3 = w[e + 3];
        acc += w0 * X[(size_t)c0 * FF + f];
        acc += w1 * X[(size_t)c1 * FF + f];
        acc += w2 * X[(size_t)c2 * FF + f];
        acc += w3 * X[(size_t)c3 * FF + f];
    }
    for (; e < e1; e++) acc += w[e] * X[(size_t)col[e] * FF + f];
    size_t o = (size_t)r * FF + f;
    if (base) Y[o] = 2.f * acc - base[o];
    else      Y[o] = acc;
}

// ---------------- mma.sync bf16x3 GEMM ----------------
// C(n x No) = [A0|A1|A2](n x kblocks*128) @ BT^T + bias.  BT is [No][ldb] row-major.
// BM=128, BN=128, BK=32, 256 threads, 8 warps each 64x32.
#define LDS_EL 40          // smem row stride in bf16 elements (80B, conflict-free ldmatrix)
#define STAGE_BYTES (4 * 128 * LDS_EL * 2)   // Ahi,Alo,Bhi,Blo = 40960
#define GEMM_SMEM_BYTES (1024 + 2 * STAGE_BYTES)
__global__ void __launch_bounds__(256) k_gemm_mma(
    const float* __restrict__ A0, const float* __restrict__ A1, const float* __restrict__ A2,
    int kblocks, const float* __restrict__ BT, int ldb,
    const float* __restrict__ bias, float* __restrict__ C, int n, int No, int act) {
    extern __shared__ char smem[];
    float* bias_s = (float*)smem;
    uint32_t sb = smem_u32(smem);

    const int tid = threadIdx.x;
    const int lane = tid & 31, wid = tid >> 5;
    const int wm = wid & 1, wn = wid >> 1;      // warp grid 2 x 4
    const int m0 = blockIdx.x * 128, n0 = blockIdx.y * 128;

    if (tid < 128) bias_s[tid] = bias[n0 + tid];

    const float* Ap[3] = {A0, A1, A2};
    const int nch = kblocks * 4;

    // per-thread load coords: A/B rows t>>1, k-half (t&1)*16
    const int ldr = tid >> 1;
    const int ldk = (tid & 1) * 16;
    const int garow = m0 + ldr;
    const bool aval = garow < n;
    const float* gb_row = BT + (size_t)(n0 + ldr) * ldb + ldk;

    // smem byte offsets
    const uint32_t OFF_ST[2] = {1024u, 1024u + STAGE_BYTES};
    const uint32_t OA_HI = 0, OA_LO = 128 * LDS_EL * 2, OB_HI = 2 * 128 * LDS_EL * 2,
                   OB_LO = 3 * 128 * LDS_EL * 2;

    // ldmatrix per-lane addresses (element offsets)
    const int a_row = wm * 64 + (lane & 15);
    const int a_koff = (lane >> 4) * 8;
    const int b_row = wn * 32 + (lane >> 4) * 8 + (lane & 7);
    const int b_koff = ((lane >> 3) & 1) * 8;

    float acc[4][4][4];
#pragma unroll
    for (int i = 0; i < 4; i++)
#pragma unroll
        for (int j = 0; j < 4; j++)
#pragma unroll
            for (int q = 0; q < 4; q++) acc[i][j][q] = 0.f;

    float4 avld[4], bvld[4];
    // prologue: load chunk 0
    {
        const float* ga = Ap[0] + (size_t)garow * 128 + ldk;
#pragma unroll
        for (int q = 0; q < 4; q++)
            avld[q] = aval ? *(const float4*)(ga + q * 4) : make_float4(0.f, 0.f, 0.f, 0.f);
#pragma unroll
        for (int q = 0; q < 4; q++) bvld[q] = *(const float4*)(gb_row + q * 4);
    }
    // store chunk 0 into stage 0
    {
        uint32_t base = OFF_ST[0];
        uint32_t ro = (uint32_t)(ldr * LDS_EL + ldk) * 2;
        uint32_t h[8], l[8];
#pragma unroll
        for (int q = 0; q < 4; q++) {
            split2(avld[q].x, avld[q].y, h[q * 2], l[q * 2]);
            split2(avld[q].z, avld[q].w, h[q * 2 + 1], l[q * 2 + 1]);
        }
        *(uint4*)(smem + base + OA_HI + ro)      = make_uint4(h[0], h[1], h[2], h[3]);
        *(uint4*)(smem + base + OA_HI + ro + 16) = make_uint4(h[4], h[5], h[6], h[7]);
        *(uint4*)(smem + base + OA_LO + ro)      = make_uint4(l[0], l[1], l[2], l[3]);
        *(uint4*)(smem + base + OA_LO + ro + 16) = make_uint4(l[4], l[5], l[6], l[7]);
#pragma unroll
        for (int q = 0; q < 4; q++) {
            split2(bvld[q].x, bvld[q].y, h[q * 2], l[q * 2]);
            split2(bvld[q].z, bvld[q].w, h[q * 2 + 1], l[q * 2 + 1]);
        }
        *(uint4*)(smem + base + OB_HI + ro)      = make_uint4(h[0], h[1], h[2], h[3]);
        *(uint4*)(smem + base + OB_HI + ro + 16) = make_uint4(h[4], h[5], h[6], h[7]);
        *(uint4*)(smem + base + OB_LO + ro)      = make_uint4(l[0], l[1], l[2], l[3]);
        *(uint4*)(smem + base + OB_LO + ro + 16) = make_uint4(l[4], l[5], l[6], l[7]);
    }
    __syncthreads();

    for (int cb = 0; cb < nch; cb++) {
        const int stage = cb & 1;
        // prefetch next chunk to regs
        if (cb + 1 < nch) {
            const float* ga = Ap[(cb + 1) >> 2] + (size_t)garow * 128 + ((cb + 1) & 3) * 32 + ldk;
#pragma unroll
            for (int q = 0; q < 4; q++)
                avld[q] = aval ? *(const float4*)(ga + q * 4) : make_float4(0.f, 0.f, 0.f, 0.f);
            const float* gb = gb_row + (cb + 1) * 32;
#pragma unroll
            for (int q = 0; q < 4; q++) bvld[q] = *(const float4*)(gb + q * 4);
        }
        // compute on current stage
        const uint32_t base = sb + OFF_ST[stage];
#pragma unroll
        for (int ks = 0; ks < 32; ks += 16) {
            uint32_t ah[4][4], al[4][4], bh[4][2], bl[4][2];
#pragma unroll
            for (int mi = 0; mi < 4; mi++) {
                uint32_t ra = base + OA_HI + (uint32_t)((a_row + mi * 16) * LDS_EL + ks + a_koff) * 2;
                ldm_x4(ah[mi][0], ah[mi][1], ah[mi][2], ah[mi][3], ra);
                uint32_t rl = base + OA_LO + (uint32_t)((a_row + mi * 16) * LDS_EL + ks + a_koff) * 2;
                ldm_x4(al[mi][0], al[mi][1], al[mi][2], al[mi][3], rl);
            }
#pragma unroll
            for (int g = 0; g < 2; g++) {
                uint32_t rb = base + OB_HI + (uint32_t)((b_row + g * 16) * LDS_EL + ks + b_koff) * 2;
                ldm_x4(bh[g * 2][0], bh[g * 2][1], bh[g * 2 + 1][0], bh[g * 2 + 1][1], rb);
                uint32_t rbl = base + OB_LO + (uint32_t)((b_row + g * 16) * LDS_EL + ks + b_koff) * 2;
                ldm_x4(bl[g * 2][0], bl[g * 2][1], bl[g * 2 + 1][0], bl[g * 2 + 1][1], rbl);
            }
#pragma unroll
            for (int mi = 0; mi < 4; mi++)
#pragma unroll
                for (int nj = 0; nj < 4; nj++) {
                    mma_bf16(acc[mi][nj], ah[mi], bh[nj]);
                    mma_bf16(acc[mi][nj], ah[mi], bl[nj]);
                    mma_bf16(acc[mi][nj], al[mi], bh[nj]);
                }
        }
        // store next chunk
        if (cb + 1 < nch) {
            uint32_t sbase = OFF_ST[stage ^ 1];
            uint32_t ro = (uint32_t)(ldr * LDS_EL + ldk) * 2;
            uint32_t h[8], l[8];
#pragma unroll
            for (int q = 0; q < 4; q++) {
                split2(avld[q].x, avld[q].y, h[q * 2], l[q * 2]);
                split2(avld[q].z, avld[q].w, h[q * 2 + 1], l[q * 2 + 1]);
            }
            *(uint4*)(smem + sbase + OA_HI + ro)      = make_uint4(h[0], h[1], h[2], h[3]);
            *(uint4*)(smem + sbase + OA_HI + ro + 16) = make_uint4(h[4], h[5], h[6], h[7]);
            *(uint4*)(smem + sbase + OA_LO + ro)      = make_uint4(l[0], l[1], l[2], l[3]);
            *(uint4*)(smem + sbase + OA_LO + ro + 16) = make_uint4(l[4], l[5], l[6], l[7]);
#pragma unroll
            for (int q = 0; q < 4; q++) {
                split2(bvld[q].x, bvld[q].y, h[q * 2], l[q * 2]);
                split2(bvld[q].z, bvld[q].w, h[q * 2 + 1], l[q * 2 + 1]);
            }
            *(uint4*)(smem + sbase + OB_HI + ro)      = make_uint4(h[0], h[1], h[2], h[3]);
            *(uint4*)(smem + sbase + OB_HI + ro + 16) = make_uint4(h[4], h[5], h[6], h[7]);
            *(uint4*)(smem + sbase + OB_LO + ro)      = make_uint4(l[0], l[1], l[2], l[3]);
            *(uint4*)(smem + sbase + OB_LO + ro + 16) = make_uint4(l[4], l[5], l[6], l[7]);
        }
        __syncthreads();
    }

    // epilogue
#pragma unroll
    for (int mi = 0; mi < 4; mi++) {
        int r0 = m0 + wm * 64 + mi * 16 + (lane >> 2);
#pragma unroll
        for (int nj = 0; nj < 4; nj++) {
            int c = wn * 32 + nj * 8 + (lane & 3) * 2;
            float b0 = bias_s[c], b1 = bias_s[c + 1];
            if (r0 < n) {
                float2 o = make_float2(acc[mi][nj][0] + b0, acc[mi][nj][1] + b1);
                if (act) { o.x = fmaxf(o.x, 0.f); o.y = fmaxf(o.y, 0.f); }
                *(float2*)(C + (size_t)r0 * No + n0 + c) = o;
            }
            if (r0 + 8 < n) {
                float2 o = make_float2(acc[mi][nj][2] + b0, acc[mi][nj][3] + b1);
                if (act) { o.x = fmaxf(o.x, 0.f); o.y = fmaxf(o.y, 0.f); }
                *(float2*)(C + (size_t)(r0 + 8) * No + n0 + c) = o;
            }
        }
    }
}

// ---------------- weight packing (transposed: [No][K]) ----------------
__global__ void k_packT(const float* __restrict__ Wxz, const float* __restrict__ Wxr,
                        const float* __restrict__ Wxh, const float* __restrict__ Whz,
                        const float* __restrict__ Whr, const float* __restrict__ Whh,
                        const float* __restrict__ Wd1, const float* __restrict__ Wd2,
                        const float* __restrict__ bxz, const float* __restrict__ bxr,
                        const float* __restrict__ bxh, const float* __restrict__ bhz,
                        const float* __restrict__ bhr,
                        float* __restrict__ WxT, float* __restrict__ WhT,
                        float* __restrict__ WhhT, float* __restrict__ Wd1T,
                        float* __restrict__ Wd2T, float* __restrict__ bx,
                        float* __restrict__ bh) {
    int i = blockIdx.x * blockDim.x + threadIdx.x;
    if (i < 384 * 384) {
        int no = i / 384, k = i % 384;
        int kb = k >> 7, fi = k & 127, fo = no & 127;
        const float* W = (no < 128) ? Wxz : (no < 256) ? Wxr : Wxh;
        WxT[i] = W[kb * 16384 + fi * 128 + fo];
    }
    if (i < 256 * 384) {
        int no = i / 384, k = i % 384;
        int kb = k >> 7, fi = k & 127, fo = no & 127;
        const float* W = (no < 128) ? Whz : Whr;
        WhT[i] = W[kb * 16384 + fi * 128 + fo];
    }
    if (i < 128 * 384) {
        int no = i / 384, k = i % 384;
        int kb = k >> 7, fi = k & 127;
        WhhT[i] = Whh[kb * 16384 + fi * 128 + no];
    }
    if (i < 128 * 128) {
        int no = i / 128, k = i % 128;
        Wd1T[i] = Wd1[k * 128 + no];
        Wd2T[i] = Wd2[k * 128 + no];
    }
    if (i < 384) bx[i] = (i < 128) ? bxz[i] : ((i < 256) ? bxr[i - 128] : bxh[i - 256]);
    if (i < 256) bh[i] = (i < 128) ? bhz[i] : bhr[i - 128];
}

// ---------------- gates ----------------
__global__ void k_gates1(const float* __restrict__ Gx, const float* __restrict__ Gh,
                         const float* __restrict__ H, float* __restrict__ Z,
                         float* __restrict__ HR, int total) {
    int i = blockIdx.x * blockDim.x + threadIdx.x;
    if (i >= total) return;
    int row = i >> 7, c = i & 127;
    size_t bxo = (size_t)row * 384, bho = (size_t)row * 256;
    float z = 1.f / (1.f + expf(-(Gx[bxo + c] + Gh[bho + c])));
    float r = 1.f / (1.f + expf(-(Gx[bxo + 128 + c] + Gh[bho + 128 + c])));
    Z[i] = z;
    HR[i] = H[i] * r;
}
__global__ void k_gates2(const float* __restrict__ Gx, const float* __restrict__ Ghh,
                         const float* __restrict__ Z, float* __restrict__ H, int total) {
    int i = blockIdx.x * blockDim.x + threadIdx.x;
    if (i >= total) return;
    int row = i >> 7, c = i & 127;
    float ht = tanhf(Gx[(size_t)row * 384 + 256 + c] + Ghh[i]);
    float z = Z[i];
    H[i] = z * H[i] + (1.f - z) * ht;
}

// ---------------- driver ----------------
extern "C" void kernel_launch(void* const* d_in, const int* in_sizes, int n_in,
                              void* d_out, int out_size) {
    const float* x   = (const float*)d_in[0];
    const int*   ei  = (const int*)d_in[1];   // int32 (JAX x64 disabled)
    const float* Wxz = (const float*)d_in[2];
    const float* Whz = (const float*)d_in[3];
    const float* Wxr = (const float*)d_in[4];
    const float* Whr = (const float*)d_in[5];
    const float* Wxh = (const float*)d_in[6];
    const float* Whh = (const float*)d_in[7];
    const float* bxz = (const float*)d_in[8];
    const float* bhz = (const float*)d_in[9];
    const float* bxr = (const float*)d_in[10];
    const float* bhr = (const float*)d_in[11];
    const float* bxh = (const float*)d_in[12];
    const float* bhh = (const float*)d_in[13];
    const float* Wd1 = (const float*)d_in[14];
    const float* bd1 = (const float*)d_in[15];
    const float* Wd2 = (const float*)d_in[16];
    const float* bd2 = (const float*)d_in[17];
    float* out = (float*)d_out;
    (void)in_sizes; (void)n_in; (void)out_size;

    int *p_deg, *p_cnt, *p_rowoff, *p_cursor, *p_col;
    float *p_dinv, *p_w, *p_Tx1, *p_Tx2, *p_H, *p_Gx, *p_Gh, *p_Ghh, *p_Z, *p_HR, *p_D1;
    float *p_WxT, *p_WhT, *p_WhhT, *p_Wd1T, *p_Wd2T, *p_bx, *p_bh;
    cudaGetSymbolAddress((void**)&p_deg, g_deg);
    cudaGetSymbolAddress((void**)&p_cnt, g_cnt);
    cudaGetSymbolAddress((void**)&p_rowoff, g_rowoff);
    cudaGetSymbolAddress((void**)&p_cursor, g_cursor);
    cudaGetSymbolAddress((void**)&p_col, g_col);
    cudaGetSymbolAddress((void**)&p_dinv, g_dinv);
    cudaGetSymbolAddress((void**)&p_w, g_w);
    cudaGetSymbolAddress((void**)&p_Tx1, g_Tx1);
    cudaGetSymbolAddress((void**)&p_Tx2, g_Tx2);
    cudaGetSymbolAddress((void**)&p_H, g_H);
    cudaGetSymbolAddress((void**)&p_Gx, g_Gx);
    cudaGetSymbolAddress((void**)&p_Gh, g_Gh);
    cudaGetSymbolAddress((void**)&p_Ghh, g_Ghh);
    cudaGetSymbolAddress((void**)&p_Z, g_Z);
    cudaGetSymbolAddress((void**)&p_HR, g_HR);
    cudaGetSymbolAddress((void**)&p_D1, g_D1);
    cudaGetSymbolAddress((void**)&p_WxT, g_WxT);
    cudaGetSymbolAddress((void**)&p_WhT, g_WhT);
    cudaGetSymbolAddress((void**)&p_WhhT, g_WhhT);
    cudaGetSymbolAddress((void**)&p_Wd1T, g_Wd1T);
    cudaGetSymbolAddress((void**)&p_Wd2T, g_Wd2T);
    cudaGetSymbolAddress((void**)&p_bx, g_bx);
    cudaGetSymbolAddress((void**)&p_bh, g_bh);

    cudaFuncSetAttribute(k_gemm_mma, cudaFuncAttributeMaxDynamicSharedMemorySize,
                         GEMM_SMEM_BYTES);

    const int threads = 256;
    const int gE = (EE + threads - 1) / threads;
    const int gN = (NN + threads - 1) / threads;
    const int gNF = (NN * FF + threads - 1) / threads;
    dim3 spmmBlk(128, 2);
    int spmmGrid = (NN + 1) / 2;
    const int MB = (NN + 127) / 128;  // 391 row tiles

    k_packT<<<(384 * 384 + threads - 1) / threads, threads>>>(
        Wxz, Wxr, Wxh, Whz, Whr, Whh, Wd1, Wd2, bxz, bxr, bxh, bhz, bhr,
        p_WxT, p_WhT, p_WhhT, p_Wd1T, p_Wd2T, p_bx, p_bh);
    cudaMemsetAsync(p_H, 0, (size_t)NN * FF * sizeof(float));

    for (int t = 0; t < TT; t++) {
        const int* src = ei + (size_t)t * 2 * EE;
        const int* dst = src + EE;
        const float* xt = x + (size_t)t * NN * FF;

        cudaMemsetAsync(p_deg, 0, NN * sizeof(int));
        cudaMemsetAsync(p_cnt, 0, NN * sizeof(int));
        k_deg<<<gE, threads>>>(src, p_deg, EE);
        k_cnt<<<gE, threads>>>(dst, p_cnt, EE);
        k_dinv<<<gN, threads>>>(p_deg, p_dinv, NN);
        k_scan<<<1, 1024>>>(p_cnt, p_rowoff, NN);
        cudaMemcpyAsync(p_cursor, p_rowoff, NN * sizeof(int), cudaMemcpyDeviceToDevice);
        k_scatter<<<gE, threads>>>(src, dst, p_dinv, p_cursor, p_col, p_w, EE);

        // x path
        k_spmm<<<spmmGrid, spmmBlk>>>(p_rowoff, p_col, p_w, xt, nullptr, p_Tx1, NN);
        k_spmm<<<spmmGrid, spmmBlk>>>(p_rowoff, p_col, p_w, p_Tx1, xt, p_Tx2, NN);
        k_gemm_mma<<<dim3(MB, 3), 256, GEMM_SMEM_BYTES>>>(
            xt, p_Tx1, p_Tx2, 3, p_WxT, 384, p_bx, p_Gx, NN, 384, 0);
        // H path
        k_spmm<<<spmmGrid, spmmBlk>>>(p_rowoff, p_col, p_w, p_H, nullptr, p_Tx1, NN);
        k_spmm<<<spmmGrid, spmmBlk>>>(p_rowoff, p_col, p_w, p_Tx1, p_H, p_Tx2, NN);
        k_gemm_mma<<<dim3(MB, 2), 256, GEMM_SMEM_BYTES>>>(
            p_H, p_Tx1, p_Tx2, 3, p_WhT, 384, p_bh, p_Gh, NN, 256, 0);
        // gates Z,R; HR = H*R
        k_gates1<<<gNF, threads>>>(p_Gx, p_Gh, p_H, p_Z, p_HR, NN * FF);
        // HR path
        k_spmm<<<spmmGrid, spmmBlk>>>(p_rowoff, p_col, p_w, p_HR, nullptr, p_Tx1, NN);
        k_spmm<<<spmmGrid, spmmBlk>>>(p_rowoff, p_col, p_w, p_Tx1, p_HR, p_Tx2, NN);
        k_gemm_mma<<<dim3(MB, 1), 256, GEMM_SMEM_BYTES>>>(
            p_HR, p_Tx1, p_Tx2, 3, p_WhhT, 384, bhh, p_Ghh, NN, 128, 0);
        // H update
        k_gates2<<<gNF, threads>>>(p_Gx, p_Ghh, p_Z, p_H, NN * FF);
    }

    // decoder
    k_gemm_mma<<<dim3(MB, 1), 256, GEMM_SMEM_BYTES>>>(
        p_H, nullptr, nullptr, 1, p_Wd1T, 128, bd1, p_D1, NN, 128, 1);
    k_gemm_mma<<<dim3(MB, 1), 256, GEMM_SMEM_BYTES>>>(
        p_D1, nullptr, nullptr, 1, p_Wd2T, 128, bd2, out, NN, 128, 0);
    cudaMemcpyAsync(out + (size_t)NN * FF, p_H, (size_t)NN * FF * sizeof(float),
                    cudaMemcpyDeviceToDevice);
}

// round 6
// speedup vs baseline: 1.8170x; 1.3941x over previous
#include <cuda_runtime.h>
#include <cuda_fp16.h>
#include <cstdint>
#include <math.h>

#define NN 50000
#define TT 4
#define FF 128
#define EE 800000

// ---------------- scratch (static device globals; no allocation) ----------------
__device__ int    g_deg[NN];
__device__ float  g_dinv[NN];
__device__ int    g_cnt[NN];
__device__ int    g_rowoff[NN + 1];
__device__ int    g_cursor[NN];
__device__ int    g_col[EE];
__device__ float  g_w[EE];
__device__ __half g_xh[(size_t)NN * FF];
__device__ __half g_Tx1h[(size_t)NN * FF];
__device__ __half g_Tx2h[(size_t)NN * FF];
__device__ float  g_H[(size_t)NN * FF];
__device__ __half g_Hh[(size_t)NN * FF];
__device__ __half g_HRh[(size_t)NN * FF];
__device__ __half g_D1h[(size_t)NN * FF];
__device__ float  g_Gx[(size_t)NN * 384];
__device__ float  g_Gh[(size_t)NN * 256];
__device__ float  g_Ghh[(size_t)NN * FF];
__device__ float  g_Z[(size_t)NN * FF];
__device__ __half g_WxHi[384 * 384],  g_WxLo[384 * 384];    // [No][K]
__device__ __half g_WhHi[256 * 384],  g_WhLo[256 * 384];
__device__ __half g_WhhHi[128 * 384], g_WhhLo[128 * 384];
__device__ __half g_Wd1Hi[128 * 128], g_Wd1Lo[128 * 128];
__device__ __half g_Wd2Hi[128 * 128], g_Wd2Lo[128 * 128];
__device__ float  g_bx[384];
__device__ float  g_bh[256];

// ---------------- helpers ----------------
__device__ __forceinline__ uint32_t smem_u32(const void* p) {
    uint32_t a;
    asm("{ .reg .u64 t; cvta.to.shared.u64 t, %1; cvt.u32.u64 %0, t; }" : "=r"(a) : "l"(p));
    return a;
}
__device__ __forceinline__ void ldm_x4(uint32_t& r0, uint32_t& r1, uint32_t& r2, uint32_t& r3,
                                       uint32_t addr) {
    asm volatile("ldmatrix.sync.aligned.m8n8.x4.shared.b16 {%0,%1,%2,%3}, [%4];"
                 : "=r"(r0), "=r"(r1), "=r"(r2), "=r"(r3) : "r"(addr));
}
__device__ __forceinline__ void mma_f16(float* d, const uint32_t* a, const uint32_t* b) {
    asm volatile(
        "mma.sync.aligned.m16n8k16.row.col.f32.f16.f16.f32 "
        "{%0,%1,%2,%3}, {%4,%5,%6,%7}, {%8,%9}, {%0,%1,%2,%3};"
        : "+f"(d[0]), "+f"(d[1]), "+f"(d[2]), "+f"(d[3])
        : "r"(a[0]), "r"(a[1]), "r"(a[2]), "r"(a[3]), "r"(b[0]), "r"(b[1]));
}

// ---------------- graph preprocessing (edge_index is int32) ----------------
__global__ void k_hist(const int* __restrict__ src, const int* __restrict__ dst,
                       int* __restrict__ deg, int* __restrict__ cnt, int E) {
    int i = blockIdx.x * blockDim.x + threadIdx.x;
    if (i < E) {
        unsigned s = (unsigned)src[i];
        unsigned d = (unsigned)dst[i];
        if (s < NN) atomicAdd(&deg[s], 1);
        if (d < NN) atomicAdd(&cnt[d], 1);
    }
}
__global__ void k_dinv(const int* __restrict__ deg, float* __restrict__ dinv, int n) {
    int i = blockIdx.x * blockDim.x + threadIdx.x;
    if (i < n) { int d = deg[i]; dinv[i] = d > 0 ? rsqrtf((float)d) : 0.0f; }
}
// coalesced tile-looped exclusive scan (single block of 1024)
__global__ void k_scan(const int* __restrict__ cnt, int* __restrict__ rowoff, int n) {
    __shared__ int s[1024];
    __shared__ int carry;
    int tid = threadIdx.x;
    if (tid == 0) carry = 0;
    __syncthreads();
    for (int tile = 0; tile < n; tile += 1024) {
        int idx = tile + tid;
        int v = (idx < n) ? cnt[idx] : 0;
        s[tid] = v;
        __syncthreads();
#pragma unroll
        for (int off = 1; off < 1024; off <<= 1) {
            int t = (tid >= off) ? s[tid - off] : 0;
            __syncthreads();
            s[tid] += t;
            __syncthreads();
        }
        int myc = carry;
        if (idx < n) rowoff[idx] = myc + s[tid] - v;
        __syncthreads();
        if (tid == 0) carry += s[1023];
        __syncthreads();
    }
    if (tid == 0) rowoff[n] = carry;
}
__global__ void k_scatter(const int* __restrict__ src, const int* __restrict__ dst,
                          const float* __restrict__ dinv, int* __restrict__ cursor,
                          int* __restrict__ col, float* __restrict__ w, int E) {
    int i = blockIdx.x * blockDim.x + threadIdx.x;
    if (i < E) {
        unsigned s = (unsigned)src[i], d = (unsigned)dst[i];
        if (s < NN && d < NN) {
            int pos = atomicAdd(&cursor[d], 1);
            col[pos] = (int)s;
            w[pos] = -dinv[s] * dinv[d];
        }
    }
}

// ---------------- fp32 -> fp16 cast ----------------
__global__ void k_cast(const float4* __restrict__ X, __half2* __restrict__ Y, int n4) {
    int i = blockIdx.x * blockDim.x + threadIdx.x;
    if (i < n4) {
        float4 v = X[i];
        Y[2 * i]     = __floats2half2_rn(v.x, v.y);
        Y[2 * i + 1] = __floats2half2_rn(v.z, v.w);
    }
}

// ---------------- SpMM fp16: Y[r] = sum w*X[col]  (opt 2*sum - base) ----------------
__global__ void k_spmm_h(const int* __restrict__ rowoff, const int* __restrict__ col,
                         const float* __restrict__ w, const __half2* __restrict__ X,
                         const __half2* __restrict__ base, __half2* __restrict__ Y, int n) {
    int r = blockIdx.x * 4 + threadIdx.y;
    if (r >= n) return;
    int f = threadIdx.x;  // 0..63, 2 features each
    int e0 = rowoff[r], e1 = rowoff[r + 1];
    float ax = 0.f, ay = 0.f;
    int e = e0;
    for (; e + 4 <= e1; e += 4) {
        int c0 = col[e], c1 = col[e + 1], c2 = col[e + 2], c3 = col[e + 3];
        float w0 = w[e], w1 = w[e + 1], w2 = w[e + 2], w3 = w[e + 3];
        float2 v0 = __half22float2(X[(size_t)c0 * 64 + f]);
        float2 v1 = __half22float2(X[(size_t)c1 * 64 + f]);
        float2 v2 = __half22float2(X[(size_t)c2 * 64 + f]);
        float2 v3 = __half22float2(X[(size_t)c3 * 64 + f]);
        ax += w0 * v0.x + w1 * v1.x + w2 * v2.x + w3 * v3.x;
        ay += w0 * v0.y + w1 * v1.y + w2 * v2.y + w3 * v3.y;
    }
    for (; e < e1; e++) {
        float2 v = __half22float2(X[(size_t)col[e] * 64 + f]);
        float ww = w[e];
        ax += ww * v.x;
        ay += ww * v.y;
    }
    size_t o = (size_t)r * 64 + f;
    if (base) {
        float2 b = __half22float2(base[o]);
        ax = 2.f * ax - b.x;
        ay = 2.f * ay - b.y;
    }
    Y[o] = __floats2half2_rn(ax, ay);
}

// ---------------- fp16 MMA GEMM ----------------
// C(n x No) = [A0|A1|A2](n x kblocks*128) @ (Bhi+Blo)^T + bias.  B* are [No][ldb] fp16.
// BM=128, BN=128, BK=32, 256 threads, 8 warps each 64x32. 2 MMAs per logical fp32 MMA.
#define LDS_H 40                                // halves per smem row (80B)
#define TILE_B (128 * LDS_H * 2)                // 10240 bytes per operand tile
#define STAGE_B (3 * TILE_B)                    // A, Bhi, Blo
#define GEMM_SMEM_BYTES (1024 + 2 * STAGE_B)    // 62464
__global__ void __launch_bounds__(256) k_gemm_h(
    const __half* __restrict__ A0, const __half* __restrict__ A1, const __half* __restrict__ A2,
    int kblocks, const __half* __restrict__ Bhi, const __half* __restrict__ Blo, int ldb,
    const float* __restrict__ bias, float* __restrict__ C, __half* __restrict__ Ch,
    int n, int No, int act) {
    extern __shared__ char smem[];
    float* bias_s = (float*)smem;
    uint32_t sb = smem_u32(smem);

    const int tid = threadIdx.x;
    const int lane = tid & 31, wid = tid >> 5;
    const int wm = wid & 1, wn = wid >> 1;  // 2 x 4 warp grid
    const int m0 = blockIdx.x * 128, n0 = blockIdx.y * 128;

    if (tid < 128) bias_s[tid] = bias[n0 + tid];

    const __half* Ap[3] = {A0, A1, A2};
    const int nch = kblocks * 4;

    const int ldr = tid >> 1;           // 0..127
    const int ldk = (tid & 1) * 16;     // 0 or 16
    const int garow = m0 + ldr;
    const bool aval = garow < n;
    const __half* gbh_row = Bhi + (size_t)(n0 + ldr) * ldb + ldk;
    const __half* gbl_row = Blo + (size_t)(n0 + ldr) * ldb + ldk;

    const uint32_t OFF_ST[2] = {1024u, 1024u + STAGE_B};
    const uint32_t OA = 0, OBH = TILE_B, OBL = 2 * TILE_B;

    const int a_row = wm * 64 + (lane & 15);
    const int a_koff = (lane >> 4) * 8;
    const int b_row = wn * 32 + (lane >> 4) * 8 + (lane & 7);
    const int b_koff = ((lane >> 3) & 1) * 8;

    float acc[4][4][4];
#pragma unroll
    for (int i = 0; i < 4; i++)
#pragma unroll
        for (int j = 0; j < 4; j++)
#pragma unroll
            for (int q = 0; q < 4; q++) acc[i][j][q] = 0.f;

    uint4 av[2], bhv[2], blv[2];
    // prologue: load + store chunk 0
    {
        const __half* ga = Ap[0] + (size_t)garow * 128 + ldk;
        av[0] = aval ? *(const uint4*)ga : make_uint4(0, 0, 0, 0);
        av[1] = aval ? *(const uint4*)(ga + 8) : make_uint4(0, 0, 0, 0);
        bhv[0] = *(const uint4*)gbh_row;
        bhv[1] = *(const uint4*)(gbh_row + 8);
        blv[0] = *(const uint4*)gbl_row;
        blv[1] = *(const uint4*)(gbl_row + 8);
        uint32_t ro = (uint32_t)(ldr * LDS_H + ldk) * 2;
        *(uint4*)(smem + OFF_ST[0] + OA + ro) = av[0];
        *(uint4*)(smem + OFF_ST[0] + OA + ro + 16) = av[1];
        *(uint4*)(smem + OFF_ST[0] + OBH + ro) = bhv[0];
        *(uint4*)(smem + OFF_ST[0] + OBH + ro + 16) = bhv[1];
        *(uint4*)(smem + OFF_ST[0] + OBL + ro) = blv[0];
        *(uint4*)(smem + OFF_ST[0] + OBL + ro + 16) = blv[1];
    }
    __syncthreads();

    for (int cb = 0; cb < nch; cb++) {
        const int stage = cb & 1;
        if (cb + 1 < nch) {
            const __half* ga = Ap[(cb + 1) >> 2] + (size_t)garow * 128 + ((cb + 1) & 3) * 32 + ldk;
            av[0] = aval ? *(const uint4*)ga : make_uint4(0, 0, 0, 0);
            av[1] = aval ? *(const uint4*)(ga + 8) : make_uint4(0, 0, 0, 0);
            const __half* gh = gbh_row + (cb + 1) * 32;
            const __half* gl = gbl_row + (cb + 1) * 32;
            bhv[0] = *(const uint4*)gh;
            bhv[1] = *(const uint4*)(gh + 8);
            blv[0] = *(const uint4*)gl;
            blv[1] = *(const uint4*)(gl + 8);
        }
        const uint32_t base = sb + OFF_ST[stage];
#pragma unroll
        for (int ks = 0; ks < 32; ks += 16) {
            uint32_t ah[4][4], bh[4][2], bl[4][2];
#pragma unroll
            for (int mi = 0; mi < 4; mi++) {
                uint32_t ra = base + OA + (uint32_t)((a_row + mi * 16) * LDS_H + ks + a_koff) * 2;
                ldm_x4(ah[mi][0], ah[mi][1], ah[mi][2], ah[mi][3], ra);
            }
#pragma unroll
            for (int g = 0; g < 2; g++) {
                uint32_t rb = base + OBH + (uint32_t)((b_row + g * 16) * LDS_H + ks + b_koff) * 2;
                ldm_x4(bh[g * 2][0], bh[g * 2][1], bh[g * 2 + 1][0], bh[g * 2 + 1][1], rb);
                uint32_t rl = base + OBL + (uint32_t)((b_row + g * 16) * LDS_H + ks + b_koff) * 2;
                ldm_x4(bl[g * 2][0], bl[g * 2][1], bl[g * 2 + 1][0], bl[g * 2 + 1][1], rl);
            }
#pragma unroll
            for (int mi = 0; mi < 4; mi++)
#pragma unroll
                for (int nj = 0; nj < 4; nj++) {
                    mma_f16(acc[mi][nj], ah[mi], bh[nj]);
                    mma_f16(acc[mi][nj], ah[mi], bl[nj]);
                }
        }
        if (cb + 1 < nch) {
            uint32_t sbase = OFF_ST[stage ^ 1];
            uint32_t ro = (uint32_t)(ldr * LDS_H + ldk) * 2;
            *(uint4*)(smem + sbase + OA + ro) = av[0];
            *(uint4*)(smem + sbase + OA + ro + 16) = av[1];
            *(uint4*)(smem + sbase + OBH + ro) = bhv[0];
            *(uint4*)(smem + sbase + OBH + ro + 16) = bhv[1];
            *(uint4*)(smem + sbase + OBL + ro) = blv[0];
            *(uint4*)(smem + sbase + OBL + ro + 16) = blv[1];
        }
        __syncthreads();
    }

    // epilogue
#pragma unroll
    for (int mi = 0; mi < 4; mi++) {
        int r0 = m0 + wm * 64 + mi * 16 + (lane >> 2);
#pragma unroll
        for (int nj = 0; nj < 4; nj++) {
            int c = wn * 32 + nj * 8 + (lane & 3) * 2;
            float b0 = bias_s[c], b1 = bias_s[c + 1];
#pragma unroll
            for (int half = 0; half < 2; half++) {
                int r = r0 + half * 8;
                if (r < n) {
                    float o0 = acc[mi][nj][half * 2] + b0;
                    float o1 = acc[mi][nj][half * 2 + 1] + b1;
                    if (act) { o0 = fmaxf(o0, 0.f); o1 = fmaxf(o1, 0.f); }
                    if (C)  *(float2*)(C + (size_t)r * No + n0 + c) = make_float2(o0, o1);
                    if (Ch) *(__half2*)(Ch + (size_t)r * No + n0 + c) = __floats2half2_rn(o0, o1);
                }
            }
        }
    }
}

// ---------------- weight packing (transposed [No][K], fp16 hi/lo) ----------------
__device__ __forceinline__ void splitw(float v, __half* hi, __half* lo, int i) {
    __half h = __float2half_rn(v);
    hi[i] = h;
    lo[i] = __float2half_rn(v - __half2float(h));
}
__global__ void k_packT(const float* __restrict__ Wxz, const float* __restrict__ Wxr,
                        const float* __restrict__ Wxh, const float* __restrict__ Whz,
                        const float* __restrict__ Whr, const float* __restrict__ Whh,
                        const float* __restrict__ Wd1, const float* __restrict__ Wd2,
                        const float* __restrict__ bxz, const float* __restrict__ bxr,
                        const float* __restrict__ bxh, const float* __restrict__ bhz,
                        const float* __restrict__ bhr,
                        __half* WxHi, __half* WxLo, __half* WhHi, __half* WhLo,
                        __half* WhhHi, __half* WhhLo, __half* Wd1Hi, __half* Wd1Lo,
                        __half* Wd2Hi, __half* Wd2Lo,
                        float* __restrict__ bx, float* __restrict__ bh) {
    int i = blockIdx.x * blockDim.x + threadIdx.x;
    if (i < 384 * 384) {
        int no = i / 384, k = i % 384;
        int kb = k >> 7, fi = k & 127, fo = no & 127;
        const float* W = (no < 128) ? Wxz : (no < 256) ? Wxr : Wxh;
        splitw(W[kb * 16384 + fi * 128 + fo], WxHi, WxLo, i);
    }
    if (i < 256 * 384) {
        int no = i / 384, k = i % 384;
        int kb = k >> 7, fi = k & 127, fo = no & 127;
        const float* W = (no < 128) ? Whz : Whr;
        splitw(W[kb * 16384 + fi * 128 + fo], WhHi, WhLo, i);
    }
    if (i < 128 * 384) {
        int no = i / 384, k = i % 384;
        int kb = k >> 7, fi = k & 127;
        splitw(Whh[kb * 16384 + fi * 128 + no], WhhHi, WhhLo, i);
    }
    if (i < 128 * 128) {
        int no = i / 128, k = i % 128;
        splitw(Wd1[k * 128 + no], Wd1Hi, Wd1Lo, i);
        splitw(Wd2[k * 128 + no], Wd2Hi, Wd2Lo, i);
    }
    if (i < 384) bx[i] = (i < 128) ? bxz[i] : ((i < 256) ? bxr[i - 128] : bxh[i - 256]);
    if (i < 256) bh[i] = (i < 128) ? bhz[i] : bhr[i - 128];
}

// ---------------- gates ----------------
__global__ void k_gates1(const float* __restrict__ Gx, const float* __restrict__ Gh,
                         const float* __restrict__ H, float* __restrict__ Z,
                         __half* __restrict__ HRh, int total) {
    int i = blockIdx.x * blockDim.x + threadIdx.x;
    if (i >= total) return;
    int row = i >> 7, c = i & 127;
    size_t bxo = (size_t)row * 384, bho = (size_t)row * 256;
    float z = 1.f / (1.f + expf(-(Gx[bxo + c] + Gh[bho + c])));
    float r = 1.f / (1.f + expf(-(Gx[bxo + 128 + c] + Gh[bho + 128 + c])));
    Z[i] = z;
    HRh[i] = __float2half_rn(H[i] * r);
}
__global__ void k_gates2(const float* __restrict__ Gx, const float* __restrict__ Ghh,
                         const float* __restrict__ Z, float* __restrict__ H,
                         __half* __restrict__ Hh, int total) {
    int i = blockIdx.x * blockDim.x + threadIdx.x;
    if (i >= total) return;
    int row = i >> 7, c = i & 127;
    float ht = tanhf(Gx[(size_t)row * 384 + 256 + c] + Ghh[i]);
    float z = Z[i];
    float h = z * H[i] + (1.f - z) * ht;
    H[i] = h;
    Hh[i] = __float2half_rn(h);
}

// ---------------- driver ----------------
extern "C" void kernel_launch(void* const* d_in, const int* in_sizes, int n_in,
                              void* d_out, int out_size) {
    const float* x   = (const float*)d_in[0];
    const int*   ei  = (const int*)d_in[1];   // int32 (JAX x64 disabled)
    const float* Wxz = (const float*)d_in[2];
    const float* Whz = (const float*)d_in[3];
    const float* Wxr = (const float*)d_in[4];
    const float* Whr = (const float*)d_in[5];
    const float* Wxh = (const float*)d_in[6];
    const float* Whh = (const float*)d_in[7];
    const float* bxz = (const float*)d_in[8];
    const float* bhz = (const float*)d_in[9];
    const float* bxr = (const float*)d_in[10];
    const float* bhr = (const float*)d_in[11];
    const float* bxh = (const float*)d_in[12];
    const float* bhh = (const float*)d_in[13];
    const float* Wd1 = (const float*)d_in[14];
    const float* bd1 = (const float*)d_in[15];
    const float* Wd2 = (const float*)d_in[16];
    const float* bd2 = (const float*)d_in[17];
    float* out = (float*)d_out;
    (void)in_sizes; (void)n_in; (void)out_size;

    int *p_deg, *p_cnt, *p_rowoff, *p_cursor, *p_col;
    float *p_dinv, *p_w, *p_H, *p_Gx, *p_Gh, *p_Ghh, *p_Z, *p_bx, *p_bh;
    __half *p_xh, *p_Tx1h, *p_Tx2h, *p_Hh, *p_HRh, *p_D1h;
    __half *p_WxHi, *p_WxLo, *p_WhHi, *p_WhLo, *p_WhhHi, *p_WhhLo;
    __half *p_Wd1Hi, *p_Wd1Lo, *p_Wd2Hi, *p_Wd2Lo;
    cudaGetSymbolAddress((void**)&p_deg, g_deg);
    cudaGetSymbolAddress((void**)&p_cnt, g_cnt);
    cudaGetSymbolAddress((void**)&p_rowoff, g_rowoff);
    cudaGetSymbolAddress((void**)&p_cursor, g_cursor);
    cudaGetSymbolAddress((void**)&p_col, g_col);
    cudaGetSymbolAddress((void**)&p_dinv, g_dinv);
    cudaGetSymbolAddress((void**)&p_w, g_w);
    cudaGetSymbolAddress((void**)&p_xh, g_xh);
    cudaGetSymbolAddress((void**)&p_Tx1h, g_Tx1h);
    cudaGetSymbolAddress((void**)&p_Tx2h, g_Tx2h);
    cudaGetSymbolAddress((void**)&p_H, g_H);
    cudaGetSymbolAddress((void**)&p_Hh, g_Hh);
    cudaGetSymbolAddress((void**)&p_HRh, g_HRh);
    cudaGetSymbolAddress((void**)&p_D1h, g_D1h);
    cudaGetSymbolAddress((void**)&p_Gx, g_Gx);
    cudaGetSymbolAddress((void**)&p_Gh, g_Gh);
    cudaGetSymbolAddress((void**)&p_Ghh, g_Ghh);
    cudaGetSymbolAddress((void**)&p_Z, g_Z);
    cudaGetSymbolAddress((void**)&p_WxHi, g_WxHi);
    cudaGetSymbolAddress((void**)&p_WxLo, g_WxLo);
    cudaGetSymbolAddress((void**)&p_WhHi, g_WhHi);
    cudaGetSymbolAddress((void**)&p_WhLo, g_WhLo);
    cudaGetSymbolAddress((void**)&p_WhhHi, g_WhhHi);
    cudaGetSymbolAddress((void**)&p_WhhLo, g_WhhLo);
    cudaGetSymbolAddress((void**)&p_Wd1Hi, g_Wd1Hi);
    cudaGetSymbolAddress((void**)&p_Wd1Lo, g_Wd1Lo);
    cudaGetSymbolAddress((void**)&p_Wd2Hi, g_Wd2Hi);
    cudaGetSymbolAddress((void**)&p_Wd2Lo, g_Wd2Lo);
    cudaGetSymbolAddress((void**)&p_bx, g_bx);
    cudaGetSymbolAddress((void**)&p_bh, g_bh);

    cudaFuncSetAttribute(k_gemm_h, cudaFuncAttributeMaxDynamicSharedMemorySize,
                         GEMM_SMEM_BYTES);

    const int threads = 256;
    const int gE = (EE + threads - 1) / threads;
    const int gN = (NN + threads - 1) / threads;
    const int gNF = (NN * FF + threads - 1) / threads;
    const int gC = (NN * FF / 4 + threads - 1) / threads;
    dim3 spmmBlk(64, 4);
    int spmmGrid = (NN + 3) / 4;
    const int MB = (NN + 127) / 128;  // 391

    k_packT<<<(384 * 384 + threads - 1) / threads, threads>>>(
        Wxz, Wxr, Wxh, Whz, Whr, Whh, Wd1, Wd2, bxz, bxr, bxh, bhz, bhr,
        p_WxHi, p_WxLo, p_WhHi, p_WhLo, p_WhhHi, p_WhhLo,
        p_Wd1Hi, p_Wd1Lo, p_Wd2Hi, p_Wd2Lo, p_bx, p_bh);
    cudaMemsetAsync(p_H, 0, (size_t)NN * FF * sizeof(float));
    cudaMemsetAsync(p_Hh, 0, (size_t)NN * FF * sizeof(__half));

    for (int t = 0; t < TT; t++) {
        const int* src = ei + (size_t)t * 2 * EE;
        const int* dst = src + EE;
        const float* xt = x + (size_t)t * NN * FF;

        cudaMemsetAsync(p_deg, 0, NN * sizeof(int));
        cudaMemsetAsync(p_cnt, 0, NN * sizeof(int));
        k_hist<<<gE, threads>>>(src, dst, p_deg, p_cnt, EE);
        k_dinv<<<gN, threads>>>(p_deg, p_dinv, NN);
        k_scan<<<1, 1024>>>(p_cnt, p_rowoff, NN);
        cudaMemcpyAsync(p_cursor, p_rowoff, NN * sizeof(int), cudaMemcpyDeviceToDevice);
        k_scatter<<<gE, threads>>>(src, dst, p_dinv, p_cursor, p_col, p_w, EE);
        k_cast<<<gC, threads>>>((const float4*)xt, (__half2*)p_xh, NN * FF / 4);

        // x path
        k_spmm_h<<<spmmGrid, spmmBlk>>>(p_rowoff, p_col, p_w, (const __half2*)p_xh,
                                        nullptr, (__half2*)p_Tx1h, NN);
        k_spmm_h<<<spmmGrid, spmmBlk>>>(p_rowoff, p_col, p_w, (const __half2*)p_Tx1h,
                                        (const __half2*)p_xh, (__half2*)p_Tx2h, NN);
        k_gemm_h<<<dim3(MB, 3), 256, GEMM_SMEM_BYTES>>>(
            p_xh, p_Tx1h, p_Tx2h, 3, p_WxHi, p_WxLo, 384, p_bx, p_Gx, nullptr, NN, 384, 0);
        // H path
        k_spmm_h<<<spmmGrid, spmmBlk>>>(p_rowoff, p_col, p_w, (const __half2*)p_Hh,
                                        nullptr, (__half2*)p_Tx1h, NN);
        k_spmm_h<<<spmmGrid, spmmBlk>>>(p_rowoff, p_col, p_w, (const __half2*)p_Tx1h,
                                        (const __half2*)p_Hh, (__half2*)p_Tx2h, NN);
        k_gemm_h<<<dim3(MB, 2), 256, GEMM_SMEM_BYTES>>>(
            p_Hh, p_Tx1h, p_Tx2h, 3, p_WhHi, p_WhLo, 384, p_bh, p_Gh, nullptr, NN, 256, 0);
        // gates
        k_gates1<<<gNF, threads>>>(p_Gx, p_Gh, p_H, p_Z, p_HRh, NN * FF);
        // HR path
        k_spmm_h<<<spmmGrid, spmmBlk>>>(p_rowoff, p_col, p_w, (const __half2*)p_HRh,
                                        nullptr, (__half2*)p_Tx1h, NN);
        k_spmm_h<<<spmmGrid, spmmBlk>>>(p_rowoff, p_col, p_w, (const __half2*)p_Tx1h,
                                        (const __half2*)p_HRh, (__half2*)p_Tx2h, NN);
        k_gemm_h<<<dim3(MB, 1), 256, GEMM_SMEM_BYTES>>>(
            p_HRh, p_Tx1h, p_Tx2h, 3, p_WhhHi, p_WhhLo, 384, bhh, p_Ghh, nullptr, NN, 128, 0);
        // H update
        k_gates2<<<gNF, threads>>>(p_Gx, p_Ghh, p_Z, p_H, p_Hh, NN * FF);
    }

    // decoder
    k_gemm_h<<<dim3(MB, 1), 256, GEMM_SMEM_BYTES>>>(
        p_Hh, nullptr, nullptr, 1, p_Wd1Hi, p_Wd1Lo, 128, bd1, nullptr, p_D1h, NN, 128, 1);
    k_gemm_h<<<dim3(MB, 1), 256, GEMM_SMEM_BYTES>>>(
        p_D1h, nullptr, nullptr, 1, p_Wd2Hi, p_Wd2Lo, 128, bd2, out, nullptr, NN, 128, 0);
    cudaMemcpyAsync(out + (size_t)NN * FF, p_H, (size_t)NN * FF * sizeof(float),
                    cudaMemcpyDeviceToDevice);
}

// round 7
// speedup vs baseline: 2.0097x; 1.1061x over previous
#include <cuda_runtime.h>
#include <cuda_fp16.h>
#include <cstdint>
#include <math.h>

#define NN 50000
#define TT 4
#define FF 128
#define EE 800000
#define SCAN_B 256
#define NB ((NN + SCAN_B - 1) / SCAN_B)   // 196

// ---------------- scratch (static device globals; no allocation) ----------------
__device__ int    g_deg[NN];
__device__ float  g_dinv[NN];
__device__ int    g_cnt[NN];
__device__ int    g_bsum[NB];
__device__ int    g_rowoff[NN + 1];
__device__ int    g_cursor[NN];
__device__ int    g_col[EE];
__device__ float  g_w[EE];
__device__ __half g_xh[(size_t)TT * NN * FF];
__device__ __half g_Tx1h[(size_t)NN * FF];
__device__ __half g_Tx2h[(size_t)NN * FF];
__device__ float  g_H[(size_t)NN * FF];
__device__ __half g_Hh[(size_t)NN * FF];
__device__ __half g_HRh[(size_t)NN * FF];
__device__ __half g_D1h[(size_t)NN * FF];
__device__ float  g_Gx[(size_t)NN * 384];
__device__ float  g_Gh[(size_t)NN * 256];
__device__ float  g_Ghh[(size_t)NN * FF];
__device__ float  g_Z[(size_t)NN * FF];
__device__ __half g_WxHi[384 * 384],  g_WxLo[384 * 384];    // [No][K]
__device__ __half g_WhHi[256 * 384],  g_WhLo[256 * 384];
__device__ __half g_WhhHi[128 * 384], g_WhhLo[128 * 384];
__device__ __half g_Wd1Hi[128 * 128], g_Wd1Lo[128 * 128];
__device__ __half g_Wd2Hi[128 * 128], g_Wd2Lo[128 * 128];
__device__ float  g_bx[384];
__device__ float  g_bh[256];

// ---------------- helpers ----------------
__device__ __forceinline__ uint32_t smem_u32(const void* p) {
    uint32_t a;
    asm("{ .reg .u64 t; cvta.to.shared.u64 t, %1; cvt.u32.u64 %0, t; }" : "=r"(a) : "l"(p));
    return a;
}
__device__ __forceinline__ void ldm_x4(uint32_t& r0, uint32_t& r1, uint32_t& r2, uint32_t& r3,
                                       uint32_t addr) {
    asm volatile("ldmatrix.sync.aligned.m8n8.x4.shared.b16 {%0,%1,%2,%3}, [%4];"
                 : "=r"(r0), "=r"(r1), "=r"(r2), "=r"(r3) : "r"(addr));
}
__device__ __forceinline__ void mma_f16(float* d, const uint32_t* a, const uint32_t* b) {
    asm volatile(
        "mma.sync.aligned.m16n8k16.row.col.f32.f16.f16.f32 "
        "{%0,%1,%2,%3}, {%4,%5,%6,%7}, {%8,%9}, {%0,%1,%2,%3};"
        : "+f"(d[0]), "+f"(d[1]), "+f"(d[2]), "+f"(d[3])
        : "r"(a[0]), "r"(a[1]), "r"(a[2]), "r"(a[3]), "r"(b[0]), "r"(b[1]));
}

// ---------------- graph preprocessing (edge_index is int32) ----------------
__global__ void k_hist(const int* __restrict__ src, const int* __restrict__ dst,
                       int* __restrict__ deg, int* __restrict__ cnt, int E) {
    int i = blockIdx.x * blockDim.x + threadIdx.x;
    if (i < E) {
        unsigned s = (unsigned)src[i];
        unsigned d = (unsigned)dst[i];
        if (s < NN) atomicAdd(&deg[s], 1);
        if (d < NN) atomicAdd(&cnt[d], 1);
    }
}
__global__ void k_dinv(const int* __restrict__ deg, float* __restrict__ dinv, int n) {
    int i = blockIdx.x * blockDim.x + threadIdx.x;
    if (i < n) { int d = deg[i]; dinv[i] = d > 0 ? rsqrtf((float)d) : 0.0f; }
}
// ---- parallel exclusive scan: reduce -> top scan -> downsweep ----
__global__ void k_scan_part(const int* __restrict__ cnt, int* __restrict__ bsum, int n) {
    __shared__ int s[SCAN_B];
    int tid = threadIdx.x;
    int idx = blockIdx.x * SCAN_B + tid;
    s[tid] = (idx < n) ? cnt[idx] : 0;
    __syncthreads();
#pragma unroll
    for (int off = SCAN_B / 2; off > 0; off >>= 1) {
        if (tid < off) s[tid] += s[tid + off];
        __syncthreads();
    }
    if (tid == 0) bsum[blockIdx.x] = s[0];
}
__global__ void k_scan_top(int* __restrict__ bsum, int nb, int* __restrict__ rowoff, int n) {
    __shared__ int s[SCAN_B];
    int tid = threadIdx.x;
    int v = (tid < nb) ? bsum[tid] : 0;
    s[tid] = v;
    __syncthreads();
#pragma unroll
    for (int off = 1; off < SCAN_B; off <<= 1) {
        int t = (tid >= off) ? s[tid - off] : 0;
        __syncthreads();
        s[tid] += t;
        __syncthreads();
    }
    if (tid < nb) bsum[tid] = s[tid] - v;       // exclusive block offsets
    if (tid == SCAN_B - 1) rowoff[n] = s[SCAN_B - 1];  // grand total
}
__global__ void k_scan_down(const int* __restrict__ cnt, const int* __restrict__ bsum,
                            int* __restrict__ rowoff, int n) {
    __shared__ int s[SCAN_B];
    int tid = threadIdx.x;
    int idx = blockIdx.x * SCAN_B + tid;
    int v = (idx < n) ? cnt[idx] : 0;
    s[tid] = v;
    __syncthreads();
#pragma unroll
    for (int off = 1; off < SCAN_B; off <<= 1) {
        int t = (tid >= off) ? s[tid - off] : 0;
        __syncthreads();
        s[tid] += t;
        __syncthreads();
    }
    if (idx < n) rowoff[idx] = bsum[blockIdx.x] + s[tid] - v;
}
__global__ void k_scatter(const int* __restrict__ src, const int* __restrict__ dst,
                          const float* __restrict__ dinv, int* __restrict__ cursor,
                          int* __restrict__ col, float* __restrict__ w, int E) {
    int i = blockIdx.x * blockDim.x + threadIdx.x;
    if (i < E) {
        unsigned s = (unsigned)src[i], d = (unsigned)dst[i];
        if (s < NN && d < NN) {
            int pos = atomicAdd(&cursor[d], 1);
            col[pos] = (int)s;
            w[pos] = -dinv[s] * dinv[d];
        }
    }
}

// ---------------- fp32 -> fp16 cast ----------------
__global__ void k_cast(const float4* __restrict__ X, __half2* __restrict__ Y, int n4) {
    int i = blockIdx.x * blockDim.x + threadIdx.x;
    if (i < n4) {
        float4 v = X[i];
        Y[2 * i]     = __floats2half2_rn(v.x, v.y);
        Y[2 * i + 1] = __floats2half2_rn(v.z, v.w);
    }
}

// ---------------- SpMM fp16: Y[r] = sum w*X[col]  (opt 2*sum - base) ----------------
__global__ void k_spmm_h(const int* __restrict__ rowoff, const int* __restrict__ col,
                         const float* __restrict__ w, const __half2* __restrict__ X,
                         const __half2* __restrict__ base, __half2* __restrict__ Y, int n) {
    int r = blockIdx.x * 4 + threadIdx.y;
    if (r >= n) return;
    int f = threadIdx.x;  // 0..63, 2 features each
    int e0 = rowoff[r], e1 = rowoff[r + 1];
    float ax = 0.f, ay = 0.f;
    int e = e0;
    for (; e + 4 <= e1; e += 4) {
        int c0 = col[e], c1 = col[e + 1], c2 = col[e + 2], c3 = col[e + 3];
        float w0 = w[e], w1 = w[e + 1], w2 = w[e + 2], w3 = w[e + 3];
        float2 v0 = __half22float2(X[(size_t)c0 * 64 + f]);
        float2 v1 = __half22float2(X[(size_t)c1 * 64 + f]);
        float2 v2 = __half22float2(X[(size_t)c2 * 64 + f]);
        float2 v3 = __half22float2(X[(size_t)c3 * 64 + f]);
        ax += w0 * v0.x + w1 * v1.x + w2 * v2.x + w3 * v3.x;
        ay += w0 * v0.y + w1 * v1.y + w2 * v2.y + w3 * v3.y;
    }
    for (; e < e1; e++) {
        float2 v = __half22float2(X[(size_t)col[e] * 64 + f]);
        float ww = w[e];
        ax += ww * v.x;
        ay += ww * v.y;
    }
    size_t o = (size_t)r * 64 + f;
    if (base) {
        float2 b = __half22float2(base[o]);
        ax = 2.f * ax - b.x;
        ay = 2.f * ay - b.y;
    }
    Y[o] = __floats2half2_rn(ax, ay);
}

// ---------------- fp16 MMA GEMM ----------------
// C(n x No) = [A0|A1|A2](n x kblocks*128) @ (Bhi+Blo)^T + bias.  B* are [No][ldb] fp16.
// BM=128, BN=128, BK=32, 256 threads, 8 warps each 64x32. 2 MMAs per logical fp32 MMA.
#define LDS_H 40                                // halves per smem row (80B)
#define TILE_B (128 * LDS_H * 2)                // 10240 bytes per operand tile
#define STAGE_B (3 * TILE_B)                    // A, Bhi, Blo
#define GEMM_SMEM_BYTES (1024 + 2 * STAGE_B)    // 62464
__global__ void __launch_bounds__(256) k_gemm_h(
    const __half* __restrict__ A0, const __half* __restrict__ A1, const __half* __restrict__ A2,
    int kblocks, const __half* __restrict__ Bhi, const __half* __restrict__ Blo, int ldb,
    const float* __restrict__ bias, float* __restrict__ C, __half* __restrict__ Ch,
    int n, int No, int act) {
    extern __shared__ char smem[];
    float* bias_s = (float*)smem;
    uint32_t sb = smem_u32(smem);

    const int tid = threadIdx.x;
    const int lane = tid & 31, wid = tid >> 5;
    const int wm = wid & 1, wn = wid >> 1;  // 2 x 4 warp grid
    const int m0 = blockIdx.x * 128, n0 = blockIdx.y * 128;

    if (tid < 128) bias_s[tid] = bias[n0 + tid];

    const __half* Ap[3] = {A0, A1, A2};
    const int nch = kblocks * 4;

    const int ldr = tid >> 1;           // 0..127
    const int ldk = (tid & 1) * 16;     // 0 or 16
    const int garow = m0 + ldr;
    const bool aval = garow < n;
    const __half* gbh_row = Bhi + (size_t)(n0 + ldr) * ldb + ldk;
    const __half* gbl_row = Blo + (size_t)(n0 + ldr) * ldb + ldk;

    const uint32_t OFF_ST[2] = {1024u, 1024u + STAGE_B};
    const uint32_t OA = 0, OBH = TILE_B, OBL = 2 * TILE_B;

    const int a_row = wm * 64 + (lane & 15);
    const int a_koff = (lane >> 4) * 8;
    const int b_row = wn * 32 + (lane >> 4) * 8 + (lane & 7);
    const int b_koff = ((lane >> 3) & 1) * 8;

    float acc[4][4][4];
#pragma unroll
    for (int i = 0; i < 4; i++)
#pragma unroll
        for (int j = 0; j < 4; j++)
#pragma unroll
            for (int q = 0; q < 4; q++) acc[i][j][q] = 0.f;

    uint4 av[2], bhv[2], blv[2];
    // prologue: load + store chunk 0
    {
        const __half* ga = Ap[0] + (size_t)garow * 128 + ldk;
        av[0] = aval ? *(const uint4*)ga : make_uint4(0, 0, 0, 0);
        av[1] = aval ? *(const uint4*)(ga + 8) : make_uint4(0, 0, 0, 0);
        bhv[0] = *(const uint4*)gbh_row;
        bhv[1] = *(const uint4*)(gbh_row + 8);
        blv[0] = *(const uint4*)gbl_row;
        blv[1] = *(const uint4*)(gbl_row + 8);
        uint32_t ro = (uint32_t)(ldr * LDS_H + ldk) * 2;
        *(uint4*)(smem + OFF_ST[0] + OA + ro) = av[0];
        *(uint4*)(smem + OFF_ST[0] + OA + ro + 16) = av[1];
        *(uint4*)(smem + OFF_ST[0] + OBH + ro) = bhv[0];
        *(uint4*)(smem + OFF_ST[0] + OBH + ro + 16) = bhv[1];
        *(uint4*)(smem + OFF_ST[0] + OBL + ro) = blv[0];
        *(uint4*)(smem + OFF_ST[0] + OBL + ro + 16) = blv[1];
    }
    __syncthreads();

    for (int cb = 0; cb < nch; cb++) {
        const int stage = cb & 1;
        if (cb + 1 < nch) {
            const __half* ga = Ap[(cb + 1) >> 2] + (size_t)garow * 128 + ((cb + 1) & 3) * 32 + ldk;
            av[0] = aval ? *(const uint4*)ga : make_uint4(0, 0, 0, 0);
            av[1] = aval ? *(const uint4*)(ga + 8) : make_uint4(0, 0, 0, 0);
            const __half* gh = gbh_row + (cb + 1) * 32;
            const __half* gl = gbl_row + (cb + 1) * 32;
            bhv[0] = *(const uint4*)gh;
            bhv[1] = *(const uint4*)(gh + 8);
            blv[0] = *(const uint4*)gl;
            blv[1] = *(const uint4*)(gl + 8);
        }
        const uint32_t base = sb + OFF_ST[stage];
#pragma unroll
        for (int ks = 0; ks < 32; ks += 16) {
            uint32_t ah[4][4], bh[4][2], bl[4][2];
#pragma unroll
            for (int mi = 0; mi < 4; mi++) {
                uint32_t ra = base + OA + (uint32_t)((a_row + mi * 16) * LDS_H + ks + a_koff) * 2;
                ldm_x4(ah[mi][0], ah[mi][1], ah[mi][2], ah[mi][3], ra);
            }
#pragma unroll
            for (int g = 0; g < 2; g++) {
                uint32_t rb = base + OBH + (uint32_t)((b_row + g * 16) * LDS_H + ks + b_koff) * 2;
                ldm_x4(bh[g * 2][0], bh[g * 2][1], bh[g * 2 + 1][0], bh[g * 2 + 1][1], rb);
                uint32_t rl = base + OBL + (uint32_t)((b_row + g * 16) * LDS_H + ks + b_koff) * 2;
                ldm_x4(bl[g * 2][0], bl[g * 2][1], bl[g * 2 + 1][0], bl[g * 2 + 1][1], rl);
            }
#pragma unroll
            for (int mi = 0; mi < 4; mi++)
#pragma unroll
                for (int nj = 0; nj < 4; nj++) {
                    mma_f16(acc[mi][nj], ah[mi], bh[nj]);
                    mma_f16(acc[mi][nj], ah[mi], bl[nj]);
                }
        }
        if (cb + 1 < nch) {
            uint32_t sbase = OFF_ST[stage ^ 1];
            uint32_t ro = (uint32_t)(ldr * LDS_H + ldk) * 2;
            *(uint4*)(smem + sbase + OA + ro) = av[0];
            *(uint4*)(smem + sbase + OA + ro + 16) = av[1];
            *(uint4*)(smem + sbase + OBH + ro) = bhv[0];
            *(uint4*)(smem + sbase + OBH + ro + 16) = bhv[1];
            *(uint4*)(smem + sbase + OBL + ro) = blv[0];
            *(uint4*)(smem + sbase + OBL + ro + 16) = blv[1];
        }
        __syncthreads();
    }

    // epilogue
#pragma unroll
    for (int mi = 0; mi < 4; mi++) {
        int r0 = m0 + wm * 64 + mi * 16 + (lane >> 2);
#pragma unroll
        for (int nj = 0; nj < 4; nj++) {
            int c = wn * 32 + nj * 8 + (lane & 3) * 2;
            float b0 = bias_s[c], b1 = bias_s[c + 1];
#pragma unroll
            for (int half = 0; half < 2; half++) {
                int r = r0 + half * 8;
                if (r < n) {
                    float o0 = acc[mi][nj][half * 2] + b0;
                    float o1 = acc[mi][nj][half * 2 + 1] + b1;
                    if (act) { o0 = fmaxf(o0, 0.f); o1 = fmaxf(o1, 0.f); }
                    if (C)  *(float2*)(C + (size_t)r * No + n0 + c) = make_float2(o0, o1);
                    if (Ch) *(__half2*)(Ch + (size_t)r * No + n0 + c) = __floats2half2_rn(o0, o1);
                }
            }
        }
    }
}

// ---------------- weight packing (transposed [No][K], fp16 hi/lo) ----------------
__device__ __forceinline__ void splitw(float v, __half* hi, __half* lo, int i) {
    __half h = __float2half_rn(v);
    hi[i] = h;
    lo[i] = __float2half_rn(v - __half2float(h));
}
__global__ void k_packT(const float* __restrict__ Wxz, const float* __restrict__ Wxr,
                        const float* __restrict__ Wxh, const float* __restrict__ Whz,
                        const float* __restrict__ Whr, const float* __restrict__ Whh,
                        const float* __restrict__ Wd1, const float* __restrict__ Wd2,
                        const float* __restrict__ bxz, const float* __restrict__ bxr,
                        const float* __restrict__ bxh, const float* __restrict__ bhz,
                        const float* __restrict__ bhr,
                        __half* WxHi, __half* WxLo, __half* WhHi, __half* WhLo,
                        __half* WhhHi, __half* WhhLo, __half* Wd1Hi, __half* Wd1Lo,
                        __half* Wd2Hi, __half* Wd2Lo,
                        float* __restrict__ bx, float* __restrict__ bh) {
    int i = blockIdx.x * blockDim.x + threadIdx.x;
    if (i < 384 * 384) {
        int no = i / 384, k = i % 384;
        int kb = k >> 7, fi = k & 127, fo = no & 127;
        const float* W = (no < 128) ? Wxz : (no < 256) ? Wxr : Wxh;
        splitw(W[kb * 16384 + fi * 128 + fo], WxHi, WxLo, i);
    }
    if (i < 256 * 384) {
        int no = i / 384, k = i % 384;
        int kb = k >> 7, fi = k & 127, fo = no & 127;
        const float* W = (no < 128) ? Whz : Whr;
        splitw(W[kb * 16384 + fi * 128 + fo], WhHi, WhLo, i);
    }
    if (i < 128 * 384) {
        int no = i / 384, k = i % 384;
        int kb = k >> 7, fi = k & 127;
        splitw(Whh[kb * 16384 + fi * 128 + no], WhhHi, WhhLo, i);
    }
    if (i < 128 * 128) {
        int no = i / 128, k = i % 128;
        splitw(Wd1[k * 128 + no], Wd1Hi, Wd1Lo, i);
        splitw(Wd2[k * 128 + no], Wd2Hi, Wd2Lo, i);
    }
    if (i < 384) bx[i] = (i < 128) ? bxz[i] : ((i < 256) ? bxr[i - 128] : bxh[i - 256]);
    if (i < 256) bh[i] = (i < 128) ? bhz[i] : bhr[i - 128];
}

// ---------------- gates ----------------
__global__ void k_gates1(const float* __restrict__ Gx, const float* __restrict__ Gh,
                         const float* __restrict__ H, float* __restrict__ Z,
                         __half* __restrict__ HRh, int total) {
    int i = blockIdx.x * blockDim.x + threadIdx.x;
    if (i >= total) return;
    int row = i >> 7, c = i & 127;
    size_t bxo = (size_t)row * 384, bho = (size_t)row * 256;
    float z = 1.f / (1.f + expf(-(Gx[bxo + c] + Gh[bho + c])));
    float r = 1.f / (1.f + expf(-(Gx[bxo + 128 + c] + Gh[bho + 128 + c])));
    Z[i] = z;
    HRh[i] = __float2half_rn(H[i] * r);
}
__global__ void k_gates2(const float* __restrict__ Gx, const float* __restrict__ Ghh,
                         const float* __restrict__ Z, float* __restrict__ H,
                         __half* __restrict__ Hh, int total) {
    int i = blockIdx.x * blockDim.x + threadIdx.x;
    if (i >= total) return;
    int row = i >> 7, c = i & 127;
    float ht = tanhf(Gx[(size_t)row * 384 + 256 + c] + Ghh[i]);
    float z = Z[i];
    float h = z * H[i] + (1.f - z) * ht;
    H[i] = h;
    Hh[i] = __float2half_rn(h);
}

// ---------------- driver ----------------
extern "C" void kernel_launch(void* const* d_in, const int* in_sizes, int n_in,
                              void* d_out, int out_size) {
    const float* x   = (const float*)d_in[0];
    const int*   ei  = (const int*)d_in[1];   // int32 (JAX x64 disabled)
    const float* Wxz = (const float*)d_in[2];
    const float* Whz = (const float*)d_in[3];
    const float* Wxr = (const float*)d_in[4];
    const float* Whr = (const float*)d_in[5];
    const float* Wxh = (const float*)d_in[6];
    const float* Whh = (const float*)d_in[7];
    const float* bxz = (const float*)d_in[8];
    const float* bhz = (const float*)d_in[9];
    const float* bxr = (const float*)d_in[10];
    const float* bhr = (const float*)d_in[11];
    const float* bxh = (const float*)d_in[12];
    const float* bhh = (const float*)d_in[13];
    const float* Wd1 = (const float*)d_in[14];
    const float* bd1 = (const float*)d_in[15];
    const float* Wd2 = (const float*)d_in[16];
    const float* bd2 = (const float*)d_in[17];
    float* out = (float*)d_out;
    (void)in_sizes; (void)n_in; (void)out_size;

    int *p_deg, *p_cnt, *p_bsum, *p_rowoff, *p_cursor, *p_col;
    float *p_dinv, *p_w, *p_H, *p_Gx, *p_Gh, *p_Ghh, *p_Z, *p_bx, *p_bh;
    __half *p_xh, *p_Tx1h, *p_Tx2h, *p_Hh, *p_HRh, *p_D1h;
    __half *p_WxHi, *p_WxLo, *p_WhHi, *p_WhLo, *p_WhhHi, *p_WhhLo;
    __half *p_Wd1Hi, *p_Wd1Lo, *p_Wd2Hi, *p_Wd2Lo;
    cudaGetSymbolAddress((void**)&p_deg, g_deg);
    cudaGetSymbolAddress((void**)&p_cnt, g_cnt);
    cudaGetSymbolAddress((void**)&p_bsum, g_bsum);
    cudaGetSymbolAddress((void**)&p_rowoff, g_rowoff);
    cudaGetSymbolAddress((void**)&p_cursor, g_cursor);
    cudaGetSymbolAddress((void**)&p_col, g_col);
    cudaGetSymbolAddress((void**)&p_dinv, g_dinv);
    cudaGetSymbolAddress((void**)&p_w, g_w);
    cudaGetSymbolAddress((void**)&p_xh, g_xh);
    cudaGetSymbolAddress((void**)&p_Tx1h, g_Tx1h);
    cudaGetSymbolAddress((void**)&p_Tx2h, g_Tx2h);
    cudaGetSymbolAddress((void**)&p_H, g_H);
    cudaGetSymbolAddress((void**)&p_Hh, g_Hh);
    cudaGetSymbolAddress((void**)&p_HRh, g_HRh);
    cudaGetSymbolAddress((void**)&p_D1h, g_D1h);
    cudaGetSymbolAddress((void**)&p_Gx, g_Gx);
    cudaGetSymbolAddress((void**)&p_Gh, g_Gh);
    cudaGetSymbolAddress((void**)&p_Ghh, g_Ghh);
    cudaGetSymbolAddress((void**)&p_Z, g_Z);
    cudaGetSymbolAddress((void**)&p_WxHi, g_WxHi);
    cudaGetSymbolAddress((void**)&p_WxLo, g_WxLo);
    cudaGetSymbolAddress((void**)&p_WhHi, g_WhHi);
    cudaGetSymbolAddress((void**)&p_WhLo, g_WhLo);
    cudaGetSymbolAddress((void**)&p_WhhHi, g_WhhHi);
    cudaGetSymbolAddress((void**)&p_WhhLo, g_WhhLo);
    cudaGetSymbolAddress((void**)&p_Wd1Hi, g_Wd1Hi);
    cudaGetSymbolAddress((void**)&p_Wd1Lo, g_Wd1Lo);
    cudaGetSymbolAddress((void**)&p_Wd2Hi, g_Wd2Hi);
    cudaGetSymbolAddress((void**)&p_Wd2Lo, g_Wd2Lo);
    cudaGetSymbolAddress((void**)&p_bx, g_bx);
    cudaGetSymbolAddress((void**)&p_bh, g_bh);

    cudaFuncSetAttribute(k_gemm_h, cudaFuncAttributeMaxDynamicSharedMemorySize,
                         GEMM_SMEM_BYTES);

    const int threads = 256;
    const int gE = (EE + threads - 1) / threads;
    const int gN = (NN + threads - 1) / threads;
    const int gNF = (NN * FF + threads - 1) / threads;
    dim3 spmmBlk(64, 4);
    int spmmGrid = (NN + 3) / 4;
    const int MB = (NN + 127) / 128;  // 391

    k_packT<<<(384 * 384 + threads - 1) / threads, threads>>>(
        Wxz, Wxr, Wxh, Whz, Whr, Whh, Wd1, Wd2, bxz, bxr, bxh, bhz, bhr,
        p_WxHi, p_WxLo, p_WhHi, p_WhLo, p_WhhHi, p_WhhLo,
        p_Wd1Hi, p_Wd1Lo, p_Wd2Hi, p_Wd2Lo, p_bx, p_bh);
    cudaMemsetAsync(p_H, 0, (size_t)NN * FF * sizeof(float));
    cudaMemsetAsync(p_Hh, 0, (size_t)NN * FF * sizeof(__half));
    // cast all timesteps of x upfront
    {
        int n4 = TT * NN * FF / 4;
        k_cast<<<(n4 + threads - 1) / threads, threads>>>(
            (const float4*)x, (__half2*)p_xh, n4);
    }

    for (int t = 0; t < TT; t++) {
        const int* src = ei + (size_t)t * 2 * EE;
        const int* dst = src + EE;
        const __half* xth = p_xh + (size_t)t * NN * FF;

        cudaMemsetAsync(p_deg, 0, NN * sizeof(int));
        cudaMemsetAsync(p_cnt, 0, NN * sizeof(int));
        k_hist<<<gE, threads>>>(src, dst, p_deg, p_cnt, EE);
        k_dinv<<<gN, threads>>>(p_deg, p_dinv, NN);
        k_scan_part<<<NB, SCAN_B>>>(p_cnt, p_bsum, NN);
        k_scan_top<<<1, SCAN_B>>>(p_bsum, NB, p_rowoff, NN);
        k_scan_down<<<NB, SCAN_B>>>(p_cnt, p_bsum, p_rowoff, NN);
        cudaMemcpyAsync(p_cursor, p_rowoff, NN * sizeof(int), cudaMemcpyDeviceToDevice);
        k_scatter<<<gE, threads>>>(src, dst, p_dinv, p_cursor, p_col, p_w, EE);

        // x path
        k_spmm_h<<<spmmGrid, spmmBlk>>>(p_rowoff, p_col, p_w, (const __half2*)xth,
                                        nullptr, (__half2*)p_Tx1h, NN);
        k_spmm_h<<<spmmGrid, spmmBlk>>>(p_rowoff, p_col, p_w, (const __half2*)p_Tx1h,
                                        (const __half2*)xth, (__half2*)p_Tx2h, NN);
        k_gemm_h<<<dim3(MB, 3), 256, GEMM_SMEM_BYTES>>>(
            xth, p_Tx1h, p_Tx2h, 3, p_WxHi, p_WxLo, 384, p_bx, p_Gx, nullptr, NN, 384, 0);
        // H path
        k_spmm_h<<<spmmGrid, spmmBlk>>>(p_rowoff, p_col, p_w, (const __half2*)p_Hh,
                                        nullptr, (__half2*)p_Tx1h, NN);
        k_spmm_h<<<spmmGrid, spmmBlk>>>(p_rowoff, p_col, p_w, (const __half2*)p_Tx1h,
                                        (const __half2*)p_Hh, (__half2*)p_Tx2h, NN);
        k_gemm_h<<<dim3(MB, 2), 256, GEMM_SMEM_BYTES>>>(
            p_Hh, p_Tx1h, p_Tx2h, 3, p_WhHi, p_WhLo, 384, p_bh, p_Gh, nullptr, NN, 256, 0);
        // gates
        k_gates1<<<gNF, threads>>>(p_Gx, p_Gh, p_H, p_Z, p_HRh, NN * FF);
        // HR path
        k_spmm_h<<<spmmGrid, spmmBlk>>>(p_rowoff, p_col, p_w, (const __half2*)p_HRh,
                                        nullptr, (__half2*)p_Tx1h, NN);
        k_spmm_h<<<spmmGrid, spmmBlk>>>(p_rowoff, p_col, p_w, (const __half2*)p_Tx1h,
                                        (const __half2*)p_HRh, (__half2*)p_Tx2h, NN);
        k_gemm_h<<<dim3(MB, 1), 256, GEMM_SMEM_BYTES>>>(
            p_HRh, p_Tx1h, p_Tx2h, 3, p_WhhHi, p_WhhLo, 384, bhh, p_Ghh, nullptr, NN, 128, 0);
        // H update
        k_gates2<<<gNF, threads>>>(p_Gx, p_Ghh, p_Z, p_H, p_Hh, NN * FF);
    }

    // decoder
    k_gemm_h<<<dim3(MB, 1), 256, GEMM_SMEM_BYTES>>>(
        p_Hh, nullptr, nullptr, 1, p_Wd1Hi, p_Wd1Lo, 128, bd1, nullptr, p_D1h, NN, 128, 1);
    k_gemm_h<<<dim3(MB, 1), 256, GEMM_SMEM_BYTES>>>(
        p_D1h, nullptr, nullptr, 1, p_Wd2Hi, p_Wd2Lo, 128, bd2, out, nullptr, NN, 128, 0);
    cudaMemcpyAsync(out + (size_t)NN * FF, p_H, (size_t)NN * FF * sizeof(float),
                    cudaMemcpyDeviceToDevice);
}